// round 4
// baseline (speedup 1.0000x reference)
#include <cuda_runtime.h>
#include <cstdint>

#define NN 10000
#define EE 100000
#define DD 768
#define HH 4
#define CC 192
#define LL 3
#define EDIMF 16
#define NRELC 10

// GEMM tiling: block 256x128, 8 warps as 4(m) x 2(n), warp tile 64x64
#define BM 256
#define BN 128
#define BK 32
#define NKT (DD / BK)     // 24
#define GSTAGES 3
#define SA 36             // A smem row stride (floats)
#define SB 136            // B smem row stride (floats): 8*qd+g banks, conflict-free
#define AS_FLOATS (BM * SA)          // 9216
#define BS_FLOATS (BK * SB)          // 4352
#define STAGE_FLOATS (AS_FLOATS + BS_FLOATS)
#define GEMM_SMEM (GSTAGES * STAGE_FLOATS * 4)   // ~159 KB

#define MAXDEG 512

// ---------------- scratch (static device globals; no allocation) ----------------
__device__ float g_bufA[NN * DD];
__device__ float g_bufB[NN * DD];
__device__ float g_q[NN * DD];
__device__ float g_k[NN * DD];
__device__ float g_v[NN * DD];
__device__ float g_skip[NN * DD];
__device__ float g_ef[EE * EDIMF];
__device__ float g_efcsr[EE * EDIMF];
__device__ float g_alpha[EE * HH];
__device__ int   g_rowptr[NN + 1];
__device__ int   g_cnt[NN];
__device__ int   g_cur[NN];
__device__ int   g_srcidx[EE];
__device__ int   g_eid[EE];

// ---------------- async copy helpers ----------------
__device__ __forceinline__ void cp16(uint32_t dst, const float* src) {
    asm volatile("cp.async.cg.shared.global [%0], [%1], 16;" ::"r"(dst),
                 "l"(__cvta_generic_to_global(src)));
}
__device__ __forceinline__ void cp_commit() { asm volatile("cp.async.commit_group;"); }
__device__ __forceinline__ void cp_wait2() { asm volatile("cp.async.wait_group 2;"); }

__device__ __forceinline__ uint32_t f2tf32(float f) {
    uint32_t u;
    asm("cvt.rna.tf32.f32 %0, %1;" : "=r"(u) : "f"(f));
    return u;
}

// tf32 mma: D(16x8) += A(16x8) * B(8x8), A row-major frag, B col-major frag
__device__ __forceinline__ void mma_tf32(float* c, const uint32_t* a, const uint32_t* b) {
    asm volatile(
        "mma.sync.aligned.m16n8k8.row.col.f32.tf32.tf32.f32 "
        "{%0,%1,%2,%3}, {%4,%5,%6,%7}, {%8,%9}, {%0,%1,%2,%3};"
        : "+f"(c[0]), "+f"(c[1]), "+f"(c[2]), "+f"(c[3])
        : "r"(a[0]), "r"(a[1]), "r"(a[2]), "r"(a[3]), "r"(b[0]), "r"(b[1]));
}

// ================= edge feature projection (also zeroes cnt/cur for CSR build) =================
__global__ void ef_kernel(const float* __restrict__ edge_attr, const float* __restrict__ rel_emb,
                          const float* __restrict__ W_edge, const float* __restrict__ b_edge,
                          float* __restrict__ ef, int* __restrict__ cnt, int* __restrict__ cur) {
    __shared__ float sW[EDIMF * EDIMF];
    __shared__ float sB[EDIMF];
    __shared__ float sR[NRELC * (EDIMF - 1)];
    int t = threadIdx.x;
    if (t < EDIMF * EDIMF) sW[t] = W_edge[t];
    if (t < EDIMF) sB[t] = b_edge[t];
    if (t < NRELC * (EDIMF - 1)) sR[t] = rel_emb[t];
    __syncthreads();
    int e = blockIdx.x * blockDim.x + t;
    if (e >= EE) return;
    if (e < NN) { cnt[e] = 0; cur[e] = 0; }
    int r = (int)edge_attr[2 * e];
    r = min(max(r, 0), NRELC - 1);
    float feat[EDIMF];
#pragma unroll
    for (int i = 0; i < EDIMF - 1; i++) feat[i] = sR[r * (EDIMF - 1) + i];
    feat[EDIMF - 1] = edge_attr[2 * e + 1];
#pragma unroll
    for (int j = 0; j < EDIMF; j++) {
        float s = sB[j];
#pragma unroll
        for (int i = 0; i < EDIMF; i++) s += feat[i] * sW[i * EDIMF + j];
        ef[(size_t)e * EDIMF + j] = s;
    }
}

// ================= CSR build =================
__global__ void count_kernel(const int* __restrict__ edge_index, int* __restrict__ cnt) {
    int e = blockIdx.x * blockDim.x + threadIdx.x;
    if (e < EE) atomicAdd(&cnt[edge_index[EE + e]], 1);
}

__global__ void scan_kernel(const int* __restrict__ cnt, int* __restrict__ rowptr) {
    __shared__ int s[1024];
    int t = threadIdx.x;
    int carry = 0;
    if (t == 0) rowptr[0] = 0;
    for (int base = 0; base < NN; base += 1024) {
        int i = base + t;
        s[t] = (i < NN) ? cnt[i] : 0;
        __syncthreads();
        for (int off = 1; off < 1024; off <<= 1) {
            int add = (t >= off) ? s[t - off] : 0;
            __syncthreads();
            s[t] += add;
            __syncthreads();
        }
        if (i < NN) rowptr[i + 1] = carry + s[t];
        int tot = s[1023];
        __syncthreads();
        carry += tot;
    }
}

__global__ void scatter_kernel(const int* __restrict__ edge_index, const int* __restrict__ rowptr,
                               int* __restrict__ cur, int* __restrict__ srcs, int* __restrict__ eid) {
    int e = blockIdx.x * blockDim.x + threadIdx.x;
    if (e >= EE) return;
    int dst = edge_index[EE + e];
    int pos = rowptr[dst] + atomicAdd(&cur[dst], 1);
    srcs[pos] = edge_index[e];
    eid[pos] = e;
}

__global__ void ef_reorder_kernel(const float* __restrict__ ef, const int* __restrict__ eid,
                                  float* __restrict__ efc) {
    int idx = blockIdx.x * blockDim.x + threadIdx.x;
    if (idx >= EE * EDIMF) return;
    int pos = idx >> 4, i = idx & 15;
    efc[idx] = ef[(size_t)eid[pos] * EDIMF + i];
}

// ================= fused QKVS GEMM via mma.sync tf32 =================
// grid (24, 40): bx/6 = weight id, bx%6 = 128-col tile; by = 256-row tile.
__global__ void __launch_bounds__(256) gemm4_kernel(
    const float* __restrict__ A,
    const float* __restrict__ Wq, const float* __restrict__ Wk,
    const float* __restrict__ Wv, const float* __restrict__ Ws,
    const float* __restrict__ b0, const float* __restrict__ b1,
    const float* __restrict__ b2, const float* __restrict__ b3,
    float* __restrict__ o0, float* __restrict__ o1,
    float* __restrict__ o2, float* __restrict__ o3) {
    extern __shared__ float sm[];
    const int t = threadIdx.x;
    const int warp = t >> 5, lane = t & 31;
    const int g = lane >> 2, qd = lane & 3;
    const int w = blockIdx.x / 6;
    const int n0 = (blockIdx.x % 6) * BN;
    const int m0 = blockIdx.y * BM;
    const int wm = warp & 3, wn = warp >> 2;  // 4(m) x 2(n) warps, 64x64 tiles

    const float* W = (w == 0 ? Wq : w == 1 ? Wk : w == 2 ? Wv : Ws);
    const float* bias = (w == 0 ? b0 : w == 1 ? b1 : w == 2 ? b2 : b3);
    float* out = (w == 0 ? o0 : w == 1 ? o1 : w == 2 ? o2 : o3);

    uint32_t smb = (uint32_t)__cvta_generic_to_shared(sm);

    float c[4][8][4];
#pragma unroll
    for (int mi = 0; mi < 4; mi++)
#pragma unroll
        for (int ni = 0; ni < 8; ni++)
#pragma unroll
            for (int r = 0; r < 4; r++) c[mi][ni][r] = 0.f;

    auto load_stage = [&](int slot, int kt) {
        int k0 = kt * BK;
        uint32_t AsB = smb + (uint32_t)(slot * STAGE_FLOATS) * 4u;
        uint32_t BsB = AsB + AS_FLOATS * 4u;
        // A: 256 rows x 8 chunks of 16B = 2048 cp16 -> 8/thread
#pragma unroll
        for (int s = 0; s < 8; s++) {
            int i = t + s * 256;
            int row = i >> 3, c4 = (i & 7) * 4;
            int grow = m0 + row;
            const float* src = A + (size_t)(grow < NN ? grow : 0) * DD + k0 + c4;
            cp16(AsB + (uint32_t)(row * SA + c4) * 4u, src);
        }
        // B: 32 k-rows x 32 chunks of 16B = 1024 cp16 -> 4/thread
#pragma unroll
        for (int s = 0; s < 4; s++) {
            int i = t + s * 256;
            int row = i >> 5, c4 = (i & 31) * 4;
            const float* src = W + (size_t)(k0 + row) * DD + n0 + c4;
            cp16(BsB + (uint32_t)(row * SB + c4) * 4u, src);
        }
    };

#pragma unroll
    for (int s = 0; s < GSTAGES; s++) {
        load_stage(s, s);
        cp_commit();
    }

    for (int kt = 0; kt < NKT; kt++) {
        cp_wait2();
        __syncthreads();
        const float* As = sm + (kt % GSTAGES) * STAGE_FLOATS;
        const float* Bs = As + AS_FLOATS;
#pragma unroll
        for (int ks = 0; ks < 4; ks++) {
            int k0s = ks * 8;
            uint32_t a[4][4], b[8][2];
#pragma unroll
            for (int mi = 0; mi < 4; mi++) {
                int mrow = wm * 64 + mi * 16 + g;
                const float* p = As + mrow * SA + k0s + qd;
                a[mi][0] = f2tf32(p[0]);
                a[mi][1] = f2tf32(p[8 * SA]);
                a[mi][2] = f2tf32(p[4]);
                a[mi][3] = f2tf32(p[8 * SA + 4]);
            }
#pragma unroll
            for (int ni = 0; ni < 8; ni++) {
                int ncol = wn * 64 + ni * 8 + g;
                const float* p = Bs + (k0s + qd) * SB + ncol;
                b[ni][0] = f2tf32(p[0]);
                b[ni][1] = f2tf32(p[4 * SB]);
            }
#pragma unroll
            for (int mi = 0; mi < 4; mi++)
#pragma unroll
                for (int ni = 0; ni < 8; ni++) mma_tf32(c[mi][ni], a[mi], b[ni]);
        }
        __syncthreads();
        if (kt + GSTAGES < NKT) load_stage(kt % GSTAGES, kt + GSTAGES);
        cp_commit();
    }

    // epilogue: write C + bias
#pragma unroll
    for (int mi = 0; mi < 4; mi++) {
#pragma unroll
        for (int rh = 0; rh < 2; rh++) {
            int grow = m0 + wm * 64 + mi * 16 + rh * 8 + g;
            if (grow >= NN) continue;
            float* orow = out + (size_t)grow * DD + n0;
#pragma unroll
            for (int ni = 0; ni < 8; ni++) {
                int col = wn * 64 + ni * 8 + 2 * qd;
                float2 val;
                val.x = c[mi][ni][rh * 2 + 0] + bias[n0 + col];
                val.y = c[mi][ni][rh * 2 + 1] + bias[n0 + col + 1];
                *(float2*)(orow + col) = val;
            }
        }
    }
}

// ================= per-destination-node attention (CSR, smem alphas, no global atomics) =================
__global__ void __launch_bounds__(256) node_attn_kernel(
    const float* __restrict__ q, const float* __restrict__ k, const float* __restrict__ v,
    const float* __restrict__ skip, const float* __restrict__ efc,
    const int* __restrict__ rowptr, const int* __restrict__ srcs,
    const float* __restrict__ We, float* __restrict__ alphas,
    float* __restrict__ out, int gelu) {
    int n = blockIdx.x;
    int t = threadIdx.x, wid = t >> 5, lane = t & 31;
    __shared__ float qs[DD];
    __shared__ float Ps[HH * EDIMF];
    __shared__ float Ss[HH * EDIMF];
    __shared__ float wred[8 * HH];
    __shared__ float mx[HH], dsum[HH], dinv[HH];
    __shared__ float s_alpha[MAXDEG * HH];

    int start = rowptr[n], end = rowptr[n + 1];
    int deg = end - start;
    // alpha storage: smem fast path, global fallback (never taken for this input)
    float* ap = (deg <= MAXDEG) ? (s_alpha - (size_t)start * HH) : (alphas);

    const float* qrow = q + (size_t)n * DD;
    for (int i = t; i < DD; i += 256) qs[i] = qrow[i];
    if (t < HH) dsum[t] = 0.f;
    __syncthreads();
    // P[h,i] = sum_c q[h*C+c] * We[i, h*C+c]
    if (t < 64) {
        int i = t >> 2, h = t & 3;
        const float* wr = We + (size_t)i * DD + h * CC;
        const float* qq = qs + h * CC;
        float s = 0.f;
#pragma unroll 8
        for (int c = 0; c < CC; c++) s = fmaf(qq[c], wr[c], s);
        Ps[h * EDIMF + i] = s;
    }
    __syncthreads();

    const float scale = 0.07216878364870322f;  // 1/sqrt(192)
    float wmax0 = -1e30f, wmax1 = -1e30f, wmax2 = -1e30f, wmax3 = -1e30f;
    // phase A: alphas (warp per edge)
    for (int e = start + wid; e < end; e += 8) {
        int src = srcs[e];
        const float* kr = k + (size_t)src * DD;
        float dots[HH];
#pragma unroll
        for (int h = 0; h < HH; h++) {
            float s = 0.f;
#pragma unroll
            for (int j = 0; j < 6; j++) {
                int c = h * CC + lane + 32 * j;
                s = fmaf(qs[c], kr[c], s);
            }
#pragma unroll
            for (int off = 16; off > 0; off >>= 1) s += __shfl_down_sync(0xffffffffu, s, off);
            dots[h] = s;
        }
        if (lane == 0) {
            const float* ee = efc + (size_t)e * EDIMF;
            float ev[EDIMF];
#pragma unroll
            for (int i = 0; i < EDIMF; i++) ev[i] = ee[i];
#pragma unroll
            for (int h = 0; h < HH; h++) {
                float ed = 0.f;
#pragma unroll
                for (int i = 0; i < EDIMF; i++) ed = fmaf(ev[i], Ps[h * EDIMF + i], ed);
                float al = (dots[h] + ed) * scale;
                ap[(size_t)e * HH + h] = al;
                if (h == 0) wmax0 = fmaxf(wmax0, al);
                if (h == 1) wmax1 = fmaxf(wmax1, al);
                if (h == 2) wmax2 = fmaxf(wmax2, al);
                if (h == 3) wmax3 = fmaxf(wmax3, al);
            }
        }
    }
    if (lane == 0) {
        wred[wid * HH + 0] = wmax0;
        wred[wid * HH + 1] = wmax1;
        wred[wid * HH + 2] = wmax2;
        wred[wid * HH + 3] = wmax3;
    }
    __syncthreads();
    if (t < HH) {
        float m = wred[t];
#pragma unroll
        for (int ww = 1; ww < 8; ww++) m = fmaxf(m, wred[ww * HH + t]);
        mx[t] = m;
    }
    __syncthreads();
    // phase B: exp + denom
    for (int e = start + t; e < end; e += 256) {
#pragma unroll
        for (int h = 0; h < HH; h++) {
            float a = expf(ap[(size_t)e * HH + h] - mx[h]);
            ap[(size_t)e * HH + h] = a;
            atomicAdd(&dsum[h], a);
        }
    }
    __syncthreads();
    if (t < HH) dinv[t] = 1.f / (dsum[t] + 1e-16f);
    __syncthreads();
    // phase C: gather-accumulate messages (thread owns 3 channels)
    int c0 = t, c1 = t + 256, c2 = t + 512;
    int h0 = c0 / CC, h1 = c1 / CC, h2 = c2 / CC;
    float a0 = 0.f, a1 = 0.f, a2 = 0.f;
    float sacc = 0.f;
    int hS = t >> 4, iS = t & 15;
    for (int e = start; e < end; e++) {
        int src = srcs[e];
        const float* vr = v + (size_t)src * DD;
        float w0 = ap[(size_t)e * HH + h0] * dinv[h0];
        float w1 = ap[(size_t)e * HH + h1] * dinv[h1];
        float w2 = ap[(size_t)e * HH + h2] * dinv[h2];
        a0 = fmaf(w0, vr[c0], a0);
        a1 = fmaf(w1, vr[c1], a1);
        a2 = fmaf(w2, vr[c2], a2);
        if (t < 64)
            sacc = fmaf(ap[(size_t)e * HH + hS] * dinv[hS], efc[(size_t)e * EDIMF + iS], sacc);
    }
    if (t < 64) Ss[hS * EDIMF + iS] = sacc;
    __syncthreads();
    // epilogue: out = msg + S@We + skip (+ gelu)
    const float* sk = skip + (size_t)n * DD;
    float* orow = out + (size_t)n * DD;
#pragma unroll
    for (int m3 = 0; m3 < 3; m3++) {
        int c = t + m3 * 256;
        float a = (m3 == 0) ? a0 : (m3 == 1) ? a1 : a2;
        int h = c / CC;
        float s = 0.f;
#pragma unroll
        for (int i = 0; i < EDIMF; i++) s = fmaf(Ss[h * EDIMF + i], We[(size_t)i * DD + c], s);
        float val = a + s + sk[c];
        if (gelu) val = 0.5f * val * (1.f + erff(val * 0.7071067811865475f));
        orow[c] = val;
    }
}

// ================= layernorm + global mean pool =================
__global__ void ln_pool_kernel(const float* __restrict__ h, float* __restrict__ out) {
    __shared__ float red[256];
    int t = threadIdx.x;
    float acc0 = 0.f, acc1 = 0.f, acc2 = 0.f;
    for (int n = blockIdx.x; n < NN; n += gridDim.x) {
        const float* row = h + (size_t)n * DD;
        float v0 = row[t], v1 = row[t + 256], v2 = row[t + 512];
        red[t] = v0 + v1 + v2;
        __syncthreads();
        for (int off = 128; off > 0; off >>= 1) {
            if (t < off) red[t] += red[t + off];
            __syncthreads();
        }
        float mu = red[0] * (1.f / DD);
        __syncthreads();
        float d0 = v0 - mu, d1 = v1 - mu, d2 = v2 - mu;
        red[t] = d0 * d0 + d1 * d1 + d2 * d2;
        __syncthreads();
        for (int off = 128; off > 0; off >>= 1) {
            if (t < off) red[t] += red[t + off];
            __syncthreads();
        }
        float rstd = rsqrtf(red[0] * (1.f / DD) + 1e-5f);
        __syncthreads();
        acc0 += d0 * rstd;
        acc1 += d1 * rstd;
        acc2 += d2 * rstd;
    }
    atomicAdd(&out[t], acc0);
    atomicAdd(&out[t + 256], acc1);
    atomicAdd(&out[t + 512], acc2);
}

__global__ void ln_final_kernel(float* __restrict__ out, const float* __restrict__ g,
                                const float* __restrict__ b) {
    int c = threadIdx.x + blockIdx.x * blockDim.x;
    if (c < DD) out[c] = out[c] * g[c] * (1.f / NN) + b[c];
}

// ================= launch =================
extern "C" void kernel_launch(void* const* d_in, const int* in_sizes, int n_in,
                              void* d_out, int out_size) {
    const float* x          = (const float*)d_in[0];
    const float* edge_attr  = (const float*)d_in[1];
    const int*   edge_index = (const int*)d_in[2];
    const float* rel_emb    = (const float*)d_in[3];
    const float* W_edge     = (const float*)d_in[4];
    const float* b_edge     = (const float*)d_in[5];
    const float* Wk         = (const float*)d_in[6];
    const float* bk         = (const float*)d_in[7];
    const float* Wq         = (const float*)d_in[8];
    const float* bq         = (const float*)d_in[9];
    const float* Wv         = (const float*)d_in[10];
    const float* bv         = (const float*)d_in[11];
    const float* We         = (const float*)d_in[12];
    const float* Wskip      = (const float*)d_in[13];
    const float* bskip      = (const float*)d_in[14];
    const float* ln_g       = (const float*)d_in[15];
    const float* ln_b       = (const float*)d_in[16];
    float* out = (float*)d_out;

    float *bufA, *bufB, *q, *k, *v, *skip, *ef, *efc, *alpha;
    int *rowptr, *cnt, *cur, *srcidx, *eid;
    cudaGetSymbolAddress((void**)&bufA, g_bufA);
    cudaGetSymbolAddress((void**)&bufB, g_bufB);
    cudaGetSymbolAddress((void**)&q, g_q);
    cudaGetSymbolAddress((void**)&k, g_k);
    cudaGetSymbolAddress((void**)&v, g_v);
    cudaGetSymbolAddress((void**)&skip, g_skip);
    cudaGetSymbolAddress((void**)&ef, g_ef);
    cudaGetSymbolAddress((void**)&efc, g_efcsr);
    cudaGetSymbolAddress((void**)&alpha, g_alpha);
    cudaGetSymbolAddress((void**)&rowptr, g_rowptr);
    cudaGetSymbolAddress((void**)&cnt, g_cnt);
    cudaGetSymbolAddress((void**)&cur, g_cur);
    cudaGetSymbolAddress((void**)&srcidx, g_srcidx);
    cudaGetSymbolAddress((void**)&eid, g_eid);

    cudaFuncSetAttribute(gemm4_kernel, cudaFuncAttributeMaxDynamicSharedMemorySize, GEMM_SMEM);

    // prep: exactly 5 launches so launch #5 (ncu -s 5 -c 1) is gemm4 of layer 0
    ef_kernel<<<(EE + 255) / 256, 256>>>(edge_attr, rel_emb, W_edge, b_edge, ef, cnt, cur);
    count_kernel<<<(EE + 255) / 256, 256>>>(edge_index, cnt);
    scan_kernel<<<1, 1024>>>(cnt, rowptr);
    scatter_kernel<<<(EE + 255) / 256, 256>>>(edge_index, rowptr, cur, srcidx, eid);
    ef_reorder_kernel<<<(EE * EDIMF + 255) / 256, 256>>>(ef, eid, efc);

    const float* hin = x;
    for (int l = 0; l < LL; l++) {
        const float* We_l = We + (size_t)l * EDIMF * DD;
        gemm4_kernel<<<dim3(24, (NN + BM - 1) / BM), 256, GEMM_SMEM>>>(
            hin,
            Wq + (size_t)l * DD * DD, Wk + (size_t)l * DD * DD,
            Wv + (size_t)l * DD * DD, Wskip + (size_t)l * DD * DD,
            bq + (size_t)l * DD, bk + (size_t)l * DD, bv + (size_t)l * DD, bskip + (size_t)l * DD,
            q, k, v, skip);
        float* hout = (l & 1) ? bufB : bufA;
        node_attn_kernel<<<NN, 256>>>(q, k, v, skip, efc, rowptr, srcidx, We_l, alpha, hout,
                                      (l < LL - 1) ? 1 : 0);
        hin = hout;
    }

    cudaMemsetAsync(out, 0, DD * sizeof(float));
    ln_pool_kernel<<<1024, 256>>>(hin, out);
    ln_final_kernel<<<3, 256>>>(out, ln_g, ln_b);
}

// round 5
// speedup vs baseline: 1.0662x; 1.0662x over previous
#include <cuda_runtime.h>
#include <cstdint>

#define NN 10000
#define EE 100000
#define DD 768
#define HH 4
#define CC 192
#define LL 3
#define EDIMF 16
#define NRELC 10

// GEMM tiling: block 128x128, 8 warps as 2(m) x 4(n), warp tile 64x32
#define BM 128
#define BN 128
#define BK 32
#define NKT (DD / BK)     // 24
#define GSTAGES 3
#define SA 36             // A smem row stride (floats): banks 4g+qd, conflict-free
#define SB 136            // B smem row stride (floats): banks 8(qd+ni)+g, conflict-free
#define AS_FLOATS (BM * SA)          // 4608
#define BS_FLOATS (BK * SB)          // 4352
#define STAGE_FLOATS (AS_FLOATS + BS_FLOATS)
#define GEMM_SMEM (GSTAGES * STAGE_FLOATS * 4)   // ~105 KB -> 2 CTA/SM

#define MAXDEG 512

// ---------------- scratch (static device globals; no allocation) ----------------
__device__ float g_bufA[NN * DD];
__device__ float g_bufB[NN * DD];
__device__ float g_q[NN * DD];
__device__ float g_k[NN * DD];
__device__ float g_v[NN * DD];
__device__ float g_skip[NN * DD];
__device__ float g_ef[EE * EDIMF];
__device__ float g_efcsr[EE * EDIMF];
__device__ float g_alpha[EE * HH];
__device__ int   g_rowptr[NN + 1];
__device__ int   g_cnt[NN];
__device__ int   g_cur[NN];
__device__ int   g_srcidx[EE];

// ---------------- async copy helpers ----------------
__device__ __forceinline__ void cp16(uint32_t dst, const float* src) {
    asm volatile("cp.async.cg.shared.global [%0], [%1], 16;" ::"r"(dst),
                 "l"(__cvta_generic_to_global(src)));
}
__device__ __forceinline__ void cp_commit() { asm volatile("cp.async.commit_group;"); }
__device__ __forceinline__ void cp_wait2() { asm volatile("cp.async.wait_group 2;"); }

__device__ __forceinline__ uint32_t f2tf32(float f) {
    uint32_t u;
    asm("cvt.rna.tf32.f32 %0, %1;" : "=r"(u) : "f"(f));
    return u;
}

// tf32 mma: D(16x8) += A(16x8) * B(8x8), A row-major frag, B col-major frag
__device__ __forceinline__ void mma_tf32(float* c, const uint32_t* a, const uint32_t* b) {
    asm volatile(
        "mma.sync.aligned.m16n8k8.row.col.f32.tf32.tf32.f32 "
        "{%0,%1,%2,%3}, {%4,%5,%6,%7}, {%8,%9}, {%0,%1,%2,%3};"
        : "+f"(c[0]), "+f"(c[1]), "+f"(c[2]), "+f"(c[3])
        : "r"(a[0]), "r"(a[1]), "r"(a[2]), "r"(a[3]), "r"(b[0]), "r"(b[1]));
}

// ================= edge feature projection (also zeroes cnt/cur for CSR build) =================
__global__ void ef_kernel(const float* __restrict__ edge_attr, const float* __restrict__ rel_emb,
                          const float* __restrict__ W_edge, const float* __restrict__ b_edge,
                          float* __restrict__ ef, int* __restrict__ cnt, int* __restrict__ cur) {
    __shared__ float sW[EDIMF * EDIMF];
    __shared__ float sB[EDIMF];
    __shared__ float sR[NRELC * (EDIMF - 1)];
    int t = threadIdx.x;
    if (t < EDIMF * EDIMF) sW[t] = W_edge[t];
    if (t < EDIMF) sB[t] = b_edge[t];
    if (t < NRELC * (EDIMF - 1)) sR[t] = rel_emb[t];
    __syncthreads();
    int e = blockIdx.x * blockDim.x + t;
    if (e >= EE) return;
    if (e < NN) { cnt[e] = 0; cur[e] = 0; }
    int r = (int)edge_attr[2 * e];
    r = min(max(r, 0), NRELC - 1);
    float feat[EDIMF];
#pragma unroll
    for (int i = 0; i < EDIMF - 1; i++) feat[i] = sR[r * (EDIMF - 1) + i];
    feat[EDIMF - 1] = edge_attr[2 * e + 1];
#pragma unroll
    for (int j = 0; j < EDIMF; j++) {
        float s = sB[j];
#pragma unroll
        for (int i = 0; i < EDIMF; i++) s += feat[i] * sW[i * EDIMF + j];
        ef[(size_t)e * EDIMF + j] = s;
    }
}

// ================= CSR build =================
__global__ void count_kernel(const int* __restrict__ edge_index, int* __restrict__ cnt) {
    int e = blockIdx.x * blockDim.x + threadIdx.x;
    if (e < EE) atomicAdd(&cnt[edge_index[EE + e]], 1);
}

__global__ void scan_kernel(const int* __restrict__ cnt, int* __restrict__ rowptr) {
    __shared__ int s[1024];
    int t = threadIdx.x;
    int carry = 0;
    if (t == 0) rowptr[0] = 0;
    for (int base = 0; base < NN; base += 1024) {
        int i = base + t;
        s[t] = (i < NN) ? cnt[i] : 0;
        __syncthreads();
        for (int off = 1; off < 1024; off <<= 1) {
            int add = (t >= off) ? s[t - off] : 0;
            __syncthreads();
            s[t] += add;
            __syncthreads();
        }
        if (i < NN) rowptr[i + 1] = carry + s[t];
        int tot = s[1023];
        __syncthreads();
        carry += tot;
    }
}

// scatter + ef reorder fused: writes CSR src list and gathers ef rows into CSR order
__global__ void scatter_kernel(const int* __restrict__ edge_index, const int* __restrict__ rowptr,
                               int* __restrict__ cur, int* __restrict__ srcs,
                               const float* __restrict__ ef, float* __restrict__ efc) {
    int e = blockIdx.x * blockDim.x + threadIdx.x;
    if (e >= EE) return;
    int dst = edge_index[EE + e];
    int pos = rowptr[dst] + atomicAdd(&cur[dst], 1);
    srcs[pos] = edge_index[e];
    const float4* s = (const float4*)(ef + (size_t)e * EDIMF);
    float4* d = (float4*)(efc + (size_t)pos * EDIMF);
    d[0] = s[0]; d[1] = s[1]; d[2] = s[2]; d[3] = s[3];
}

// ================= fused QKVS GEMM via mma.sync tf32 =================
// grid (24, 79): bx/6 = weight id, bx%6 = 128-col tile; by = 128-row tile.
__global__ void __launch_bounds__(256, 2) gemm4_kernel(
    const float* __restrict__ A,
    const float* __restrict__ Wq, const float* __restrict__ Wk,
    const float* __restrict__ Wv, const float* __restrict__ Ws,
    const float* __restrict__ b0, const float* __restrict__ b1,
    const float* __restrict__ b2, const float* __restrict__ b3,
    float* __restrict__ o0, float* __restrict__ o1,
    float* __restrict__ o2, float* __restrict__ o3) {
    extern __shared__ float sm[];
    const int t = threadIdx.x;
    const int warp = t >> 5, lane = t & 31;
    const int g = lane >> 2, qd = lane & 3;
    const int w = blockIdx.x / 6;
    const int n0 = (blockIdx.x % 6) * BN;
    const int m0 = blockIdx.y * BM;
    const int wm = warp & 1, wn = warp >> 1;  // 2(m) x 4(n) warps, 64x32 tiles

    const float* W = (w == 0 ? Wq : w == 1 ? Wk : w == 2 ? Wv : Ws);
    const float* bias = (w == 0 ? b0 : w == 1 ? b1 : w == 2 ? b2 : b3);
    float* out = (w == 0 ? o0 : w == 1 ? o1 : w == 2 ? o2 : o3);

    uint32_t smb = (uint32_t)__cvta_generic_to_shared(sm);

    float c[4][4][4];
#pragma unroll
    for (int mi = 0; mi < 4; mi++)
#pragma unroll
        for (int ni = 0; ni < 4; ni++)
#pragma unroll
            for (int r = 0; r < 4; r++) c[mi][ni][r] = 0.f;

    auto load_stage = [&](int slot, int kt) {
        int k0 = kt * BK;
        uint32_t AsB = smb + (uint32_t)(slot * STAGE_FLOATS) * 4u;
        uint32_t BsB = AsB + AS_FLOATS * 4u;
        // A: 128 rows x 8 chunks of 16B = 1024 cp16 -> 4/thread
#pragma unroll
        for (int s = 0; s < 4; s++) {
            int i = t + s * 256;
            int row = i >> 3, c4 = (i & 7) * 4;
            int grow = m0 + row;
            const float* src = A + (size_t)(grow < NN ? grow : 0) * DD + k0 + c4;
            cp16(AsB + (uint32_t)(row * SA + c4) * 4u, src);
        }
        // B: 32 k-rows x 32 chunks of 16B = 1024 cp16 -> 4/thread
#pragma unroll
        for (int s = 0; s < 4; s++) {
            int i = t + s * 256;
            int row = i >> 5, c4 = (i & 31) * 4;
            const float* src = W + (size_t)(k0 + row) * DD + n0 + c4;
            cp16(BsB + (uint32_t)(row * SB + c4) * 4u, src);
        }
    };

#pragma unroll
    for (int s = 0; s < GSTAGES; s++) {
        load_stage(s, s);
        cp_commit();
    }

    for (int kt = 0; kt < NKT; kt++) {
        cp_wait2();
        __syncthreads();
        const float* As = sm + (kt % GSTAGES) * STAGE_FLOATS;
        const float* Bs = As + AS_FLOATS;
#pragma unroll
        for (int ks = 0; ks < 4; ks++) {
            int k0s = ks * 8;
            uint32_t a[4][4], b[4][2];
#pragma unroll
            for (int mi = 0; mi < 4; mi++) {
                int mrow = wm * 64 + mi * 16 + g;
                const float* p = As + mrow * SA + k0s + qd;
                a[mi][0] = f2tf32(p[0]);
                a[mi][1] = f2tf32(p[8 * SA]);
                a[mi][2] = f2tf32(p[4]);
                a[mi][3] = f2tf32(p[8 * SA + 4]);
            }
#pragma unroll
            for (int ni = 0; ni < 4; ni++) {
                int ncol = wn * 32 + ni * 8 + g;
                const float* p = Bs + (k0s + qd) * SB + ncol;
                b[ni][0] = f2tf32(p[0]);
                b[ni][1] = f2tf32(p[4 * SB]);
            }
#pragma unroll
            for (int mi = 0; mi < 4; mi++)
#pragma unroll
                for (int ni = 0; ni < 4; ni++) mma_tf32(c[mi][ni], a[mi], b[ni]);
        }
        __syncthreads();
        if (kt + GSTAGES < NKT) load_stage(kt % GSTAGES, kt + GSTAGES);
        cp_commit();
    }

    // epilogue: write C + bias
#pragma unroll
    for (int mi = 0; mi < 4; mi++) {
#pragma unroll
        for (int rh = 0; rh < 2; rh++) {
            int grow = m0 + wm * 64 + mi * 16 + rh * 8 + g;
            if (grow >= NN) continue;
            float* orow = out + (size_t)grow * DD + n0;
#pragma unroll
            for (int ni = 0; ni < 4; ni++) {
                int col = wn * 32 + ni * 8 + 2 * qd;
                float2 val;
                val.x = c[mi][ni][rh * 2 + 0] + bias[n0 + col];
                val.y = c[mi][ni][rh * 2 + 1] + bias[n0 + col + 1];
                *(float2*)(orow + col) = val;
            }
        }
    }
}

// ================= per-destination-node attention (CSR, smem alphas, no global atomics) =================
__global__ void __launch_bounds__(256) node_attn_kernel(
    const float* __restrict__ q, const float* __restrict__ k, const float* __restrict__ v,
    const float* __restrict__ skip, const float* __restrict__ efc,
    const int* __restrict__ rowptr, const int* __restrict__ srcs,
    const float* __restrict__ We, float* __restrict__ alphas,
    float* __restrict__ out, int gelu) {
    int n = blockIdx.x;
    int t = threadIdx.x, wid = t >> 5, lane = t & 31;
    __shared__ float qs[DD];
    __shared__ float Ps[HH * EDIMF];
    __shared__ float Ss[HH * EDIMF];
    __shared__ float wred[8 * HH];
    __shared__ float mx[HH], dsum[HH], dinv[HH];
    __shared__ float s_alpha[MAXDEG * HH];

    int start = rowptr[n], end = rowptr[n + 1];
    int deg = end - start;
    // alpha storage: smem fast path, global fallback
    float* ap = (deg <= MAXDEG) ? (s_alpha - (size_t)start * HH) : (alphas);

    const float* qrow = q + (size_t)n * DD;
    for (int i = t; i < DD; i += 256) qs[i] = qrow[i];
    if (t < HH) dsum[t] = 0.f;
    __syncthreads();
    // P[h,i] = sum_c q[h*C+c] * We[i, h*C+c]
    if (t < 64) {
        int i = t >> 2, h = t & 3;
        const float* wr = We + (size_t)i * DD + h * CC;
        const float* qq = qs + h * CC;
        float s = 0.f;
#pragma unroll 8
        for (int c = 0; c < CC; c++) s = fmaf(qq[c], wr[c], s);
        Ps[h * EDIMF + i] = s;
    }
    __syncthreads();

    const float scale = 0.07216878364870322f;  // 1/sqrt(192)
    float wmax0 = -1e30f, wmax1 = -1e30f, wmax2 = -1e30f, wmax3 = -1e30f;
    // phase A: alphas (warp per edge)
    for (int e = start + wid; e < end; e += 8) {
        int src = srcs[e];
        const float* kr = k + (size_t)src * DD;
        float dots[HH];
#pragma unroll
        for (int h = 0; h < HH; h++) {
            float s = 0.f;
#pragma unroll
            for (int j = 0; j < 6; j++) {
                int c = h * CC + lane + 32 * j;
                s = fmaf(qs[c], kr[c], s);
            }
#pragma unroll
            for (int off = 16; off > 0; off >>= 1) s += __shfl_down_sync(0xffffffffu, s, off);
            dots[h] = s;
        }
        if (lane == 0) {
            const float* ee = efc + (size_t)e * EDIMF;
            float ev[EDIMF];
#pragma unroll
            for (int i = 0; i < EDIMF; i++) ev[i] = ee[i];
#pragma unroll
            for (int h = 0; h < HH; h++) {
                float ed = 0.f;
#pragma unroll
                for (int i = 0; i < EDIMF; i++) ed = fmaf(ev[i], Ps[h * EDIMF + i], ed);
                float al = (dots[h] + ed) * scale;
                ap[(size_t)e * HH + h] = al;
                if (h == 0) wmax0 = fmaxf(wmax0, al);
                if (h == 1) wmax1 = fmaxf(wmax1, al);
                if (h == 2) wmax2 = fmaxf(wmax2, al);
                if (h == 3) wmax3 = fmaxf(wmax3, al);
            }
        }
    }
    if (lane == 0) {
        wred[wid * HH + 0] = wmax0;
        wred[wid * HH + 1] = wmax1;
        wred[wid * HH + 2] = wmax2;
        wred[wid * HH + 3] = wmax3;
    }
    __syncthreads();
    if (t < HH) {
        float m = wred[t];
#pragma unroll
        for (int ww = 1; ww < 8; ww++) m = fmaxf(m, wred[ww * HH + t]);
        mx[t] = m;
    }
    __syncthreads();
    // phase B: exp + denom
    for (int e = start + t; e < end; e += 256) {
#pragma unroll
        for (int h = 0; h < HH; h++) {
            float a = expf(ap[(size_t)e * HH + h] - mx[h]);
            ap[(size_t)e * HH + h] = a;
            atomicAdd(&dsum[h], a);
        }
    }
    __syncthreads();
    if (t < HH) dinv[t] = 1.f / (dsum[t] + 1e-16f);
    __syncthreads();
    // phase C: gather-accumulate messages (thread owns 3 channels)
    int c0 = t, c1 = t + 256, c2 = t + 512;
    int h0 = c0 / CC, h1 = c1 / CC, h2 = c2 / CC;
    float a0 = 0.f, a1 = 0.f, a2 = 0.f;
    float sacc = 0.f;
    int hS = t >> 4, iS = t & 15;
    for (int e = start; e < end; e++) {
        int src = srcs[e];
        const float* vr = v + (size_t)src * DD;
        float w0 = ap[(size_t)e * HH + h0] * dinv[h0];
        float w1 = ap[(size_t)e * HH + h1] * dinv[h1];
        float w2 = ap[(size_t)e * HH + h2] * dinv[h2];
        a0 = fmaf(w0, vr[c0], a0);
        a1 = fmaf(w1, vr[c1], a1);
        a2 = fmaf(w2, vr[c2], a2);
        if (t < 64)
            sacc = fmaf(ap[(size_t)e * HH + hS] * dinv[hS], efc[(size_t)e * EDIMF + iS], sacc);
    }
    if (t < 64) Ss[hS * EDIMF + iS] = sacc;
    __syncthreads();
    // epilogue: out = msg + S@We + skip (+ gelu)
    const float* sk = skip + (size_t)n * DD;
    float* orow = out + (size_t)n * DD;
#pragma unroll
    for (int m3 = 0; m3 < 3; m3++) {
        int c = t + m3 * 256;
        float a = (m3 == 0) ? a0 : (m3 == 1) ? a1 : a2;
        int h = c / CC;
        float s = 0.f;
#pragma unroll
        for (int i = 0; i < EDIMF; i++) s = fmaf(Ss[h * EDIMF + i], We[(size_t)i * DD + c], s);
        float val = a + s + sk[c];
        if (gelu) val = 0.5f * val * (1.f + erff(val * 0.7071067811865475f));
        orow[c] = val;
    }
}

// ================= layernorm + global mean pool =================
__global__ void ln_pool_kernel(const float* __restrict__ h, float* __restrict__ out) {
    __shared__ float red[256];
    int t = threadIdx.x;
    float acc0 = 0.f, acc1 = 0.f, acc2 = 0.f;
    for (int n = blockIdx.x; n < NN; n += gridDim.x) {
        const float* row = h + (size_t)n * DD;
        float v0 = row[t], v1 = row[t + 256], v2 = row[t + 512];
        red[t] = v0 + v1 + v2;
        __syncthreads();
        for (int off = 128; off > 0; off >>= 1) {
            if (t < off) red[t] += red[t + off];
            __syncthreads();
        }
        float mu = red[0] * (1.f / DD);
        __syncthreads();
        float d0 = v0 - mu, d1 = v1 - mu, d2 = v2 - mu;
        red[t] = d0 * d0 + d1 * d1 + d2 * d2;
        __syncthreads();
        for (int off = 128; off > 0; off >>= 1) {
            if (t < off) red[t] += red[t + off];
            __syncthreads();
        }
        float rstd = rsqrtf(red[0] * (1.f / DD) + 1e-5f);
        __syncthreads();
        acc0 += d0 * rstd;
        acc1 += d1 * rstd;
        acc2 += d2 * rstd;
    }
    atomicAdd(&out[t], acc0);
    atomicAdd(&out[t + 256], acc1);
    atomicAdd(&out[t + 512], acc2);
}

__global__ void ln_final_kernel(float* __restrict__ out, const float* __restrict__ g,
                                const float* __restrict__ b) {
    int c = threadIdx.x + blockIdx.x * blockDim.x;
    if (c < DD) out[c] = out[c] * g[c] * (1.f / NN) + b[c];
}

// ================= launch =================
extern "C" void kernel_launch(void* const* d_in, const int* in_sizes, int n_in,
                              void* d_out, int out_size) {
    const float* x          = (const float*)d_in[0];
    const float* edge_attr  = (const float*)d_in[1];
    const int*   edge_index = (const int*)d_in[2];
    const float* rel_emb    = (const float*)d_in[3];
    const float* W_edge     = (const float*)d_in[4];
    const float* b_edge     = (const float*)d_in[5];
    const float* Wk         = (const float*)d_in[6];
    const float* bk         = (const float*)d_in[7];
    const float* Wq         = (const float*)d_in[8];
    const float* bq         = (const float*)d_in[9];
    const float* Wv         = (const float*)d_in[10];
    const float* bv         = (const float*)d_in[11];
    const float* We         = (const float*)d_in[12];
    const float* Wskip      = (const float*)d_in[13];
    const float* bskip      = (const float*)d_in[14];
    const float* ln_g       = (const float*)d_in[15];
    const float* ln_b       = (const float*)d_in[16];
    float* out = (float*)d_out;

    float *bufA, *bufB, *q, *k, *v, *skip, *ef, *efc, *alpha;
    int *rowptr, *cnt, *cur, *srcidx;
    cudaGetSymbolAddress((void**)&bufA, g_bufA);
    cudaGetSymbolAddress((void**)&bufB, g_bufB);
    cudaGetSymbolAddress((void**)&q, g_q);
    cudaGetSymbolAddress((void**)&k, g_k);
    cudaGetSymbolAddress((void**)&v, g_v);
    cudaGetSymbolAddress((void**)&skip, g_skip);
    cudaGetSymbolAddress((void**)&ef, g_ef);
    cudaGetSymbolAddress((void**)&efc, g_efcsr);
    cudaGetSymbolAddress((void**)&alpha, g_alpha);
    cudaGetSymbolAddress((void**)&rowptr, g_rowptr);
    cudaGetSymbolAddress((void**)&cnt, g_cnt);
    cudaGetSymbolAddress((void**)&cur, g_cur);
    cudaGetSymbolAddress((void**)&srcidx, g_srcidx);

    cudaFuncSetAttribute(gemm4_kernel, cudaFuncAttributeMaxDynamicSharedMemorySize, GEMM_SMEM);

    // prep (3 kernels) -> gemm4 of layer 0 is the 4th kernel launch = ncu capture slot
    ef_kernel<<<(EE + 255) / 256, 256>>>(edge_attr, rel_emb, W_edge, b_edge, ef, cnt, cur);
    count_kernel<<<(EE + 255) / 256, 256>>>(edge_index, cnt);
    scan_kernel<<<1, 1024>>>(cnt, rowptr);

    const float* hin = x;
    for (int l = 0; l < LL; l++) {
        const float* We_l = We + (size_t)l * EDIMF * DD;
        gemm4_kernel<<<dim3(24, (NN + BM - 1) / BM), 256, GEMM_SMEM>>>(
            hin,
            Wq + (size_t)l * DD * DD, Wk + (size_t)l * DD * DD,
            Wv + (size_t)l * DD * DD, Wskip + (size_t)l * DD * DD,
            bq + (size_t)l * DD, bk + (size_t)l * DD, bv + (size_t)l * DD, bskip + (size_t)l * DD,
            q, k, v, skip);
        if (l == 0) {
            // CSR scatter is independent of gemm4; placed here so gemm4(L0) is launch #4
            scatter_kernel<<<(EE + 255) / 256, 256>>>(edge_index, rowptr, cur, srcidx, ef, efc);
        }
        float* hout = (l & 1) ? bufB : bufA;
        node_attn_kernel<<<NN, 256>>>(q, k, v, skip, efc, rowptr, srcidx, We_l, alpha, hout,
                                      (l < LL - 1) ? 1 : 0);
        hin = hout;
    }

    cudaMemsetAsync(out, 0, DD * sizeof(float));
    ln_pool_kernel<<<1024, 256>>>(hin, out);
    ln_final_kernel<<<3, 256>>>(out, ln_g, ln_b);
}

// round 6
// speedup vs baseline: 1.3713x; 1.2861x over previous
#include <cuda_runtime.h>
#include <cstdint>

#define NN 10000
#define EE 100000
#define DD 768
#define HH 4
#define CC 192
#define LL 3
#define EDIMF 16
#define NRELC 10

// GEMM tiling: block 128x128, 8 warps as 2(m) x 4(n), warp tile 64x32
#define BM 128
#define BN 128
#define BK 32
#define NKT (DD / BK)     // 24
#define GSTAGES 3
#define SA 36
#define SB 136
#define AS_FLOATS (BM * SA)
#define BS_FLOATS (BK * SB)
#define STAGE_FLOATS (AS_FLOATS + BS_FLOATS)
#define GEMM_SMEM (GSTAGES * STAGE_FLOATS * 4)   // ~105 KB -> 2 CTA/SM

// ---------------- scratch (static device globals; no allocation) ----------------
__device__ float g_bufA[NN * DD];
__device__ float g_bufB[NN * DD];
__device__ float g_q[NN * DD];
__device__ float g_k[NN * DD];
__device__ float g_v[NN * DD];
__device__ float g_skip[NN * DD];
__device__ float g_ef[EE * EDIMF];
__device__ float g_efcsr[EE * EDIMF];
__device__ float g_alpha[EE * HH];
__device__ float g_P[NN * HH * EDIMF];
__device__ int   g_rowptr[NN + 1];
__device__ int   g_cnt[NN];
__device__ int   g_cur[NN];
__device__ int   g_srcidx[EE];
__device__ int   g_dstc[EE];

// ---------------- async copy helpers ----------------
__device__ __forceinline__ void cp16(uint32_t dst, const float* src) {
    asm volatile("cp.async.cg.shared.global [%0], [%1], 16;" ::"r"(dst),
                 "l"(__cvta_generic_to_global(src)));
}
__device__ __forceinline__ void cp_commit() { asm volatile("cp.async.commit_group;"); }
__device__ __forceinline__ void cp_wait2() { asm volatile("cp.async.wait_group 2;"); }

__device__ __forceinline__ uint32_t f2tf32(float f) {
    uint32_t u;
    asm("cvt.rna.tf32.f32 %0, %1;" : "=r"(u) : "f"(f));
    return u;
}

__device__ __forceinline__ void mma_tf32(float* c, const uint32_t* a, const uint32_t* b) {
    asm volatile(
        "mma.sync.aligned.m16n8k8.row.col.f32.tf32.tf32.f32 "
        "{%0,%1,%2,%3}, {%4,%5,%6,%7}, {%8,%9}, {%0,%1,%2,%3};"
        : "+f"(c[0]), "+f"(c[1]), "+f"(c[2]), "+f"(c[3])
        : "r"(a[0]), "r"(a[1]), "r"(a[2]), "r"(a[3]), "r"(b[0]), "r"(b[1]));
}

// ================= edge feature projection =================
__global__ void ef_kernel(const float* __restrict__ edge_attr, const float* __restrict__ rel_emb,
                          const float* __restrict__ W_edge, const float* __restrict__ b_edge,
                          float* __restrict__ ef) {
    __shared__ float sW[EDIMF * EDIMF];
    __shared__ float sB[EDIMF];
    __shared__ float sR[NRELC * (EDIMF - 1)];
    int t = threadIdx.x;
    if (t < EDIMF * EDIMF) sW[t] = W_edge[t];
    if (t < EDIMF) sB[t] = b_edge[t];
    if (t < NRELC * (EDIMF - 1)) sR[t] = rel_emb[t];
    __syncthreads();
    int e = blockIdx.x * blockDim.x + t;
    if (e >= EE) return;
    int r = (int)edge_attr[2 * e];
    r = min(max(r, 0), NRELC - 1);
    float feat[EDIMF];
#pragma unroll
    for (int i = 0; i < EDIMF - 1; i++) feat[i] = sR[r * (EDIMF - 1) + i];
    feat[EDIMF - 1] = edge_attr[2 * e + 1];
#pragma unroll
    for (int j = 0; j < EDIMF; j++) {
        float s = sB[j];
#pragma unroll
        for (int i = 0; i < EDIMF; i++) s += feat[i] * sW[i * EDIMF + j];
        ef[(size_t)e * EDIMF + j] = s;
    }
}

// ================= CSR build =================
__global__ void count_kernel(const int* __restrict__ edge_index, int* __restrict__ cnt) {
    int e = blockIdx.x * blockDim.x + threadIdx.x;
    if (e < EE) atomicAdd(&cnt[edge_index[EE + e]], 1);
}

__global__ void scan_kernel(const int* __restrict__ cnt, int* __restrict__ rowptr) {
    __shared__ int s[1024];
    int t = threadIdx.x;
    int carry = 0;
    if (t == 0) rowptr[0] = 0;
    for (int base = 0; base < NN; base += 1024) {
        int i = base + t;
        s[t] = (i < NN) ? cnt[i] : 0;
        __syncthreads();
        for (int off = 1; off < 1024; off <<= 1) {
            int add = (t >= off) ? s[t - off] : 0;
            __syncthreads();
            s[t] += add;
            __syncthreads();
        }
        if (i < NN) rowptr[i + 1] = carry + s[t];
        int tot = s[1023];
        __syncthreads();
        carry += tot;
    }
}

// scatter + ef reorder fused; also records CSR-ordered dst
__global__ void scatter_kernel(const int* __restrict__ edge_index, const int* __restrict__ rowptr,
                               int* __restrict__ cur, int* __restrict__ srcs, int* __restrict__ dstc,
                               const float* __restrict__ ef, float* __restrict__ efc) {
    int e = blockIdx.x * blockDim.x + threadIdx.x;
    if (e >= EE) return;
    int dst = edge_index[EE + e];
    int pos = rowptr[dst] + atomicAdd(&cur[dst], 1);
    srcs[pos] = edge_index[e];
    dstc[pos] = dst;
    const float4* s = (const float4*)(ef + (size_t)e * EDIMF);
    float4* d = (float4*)(efc + (size_t)pos * EDIMF);
    d[0] = s[0]; d[1] = s[1]; d[2] = s[2]; d[3] = s[3];
}

// ================= fused QKVS GEMM via mma.sync tf32 =================
__global__ void __launch_bounds__(256, 2) gemm4_kernel(
    const float* __restrict__ A,
    const float* __restrict__ Wq, const float* __restrict__ Wk,
    const float* __restrict__ Wv, const float* __restrict__ Ws,
    const float* __restrict__ b0, const float* __restrict__ b1,
    const float* __restrict__ b2, const float* __restrict__ b3,
    float* __restrict__ o0, float* __restrict__ o1,
    float* __restrict__ o2, float* __restrict__ o3) {
    extern __shared__ float sm[];
    const int t = threadIdx.x;
    const int warp = t >> 5, lane = t & 31;
    const int g = lane >> 2, qd = lane & 3;
    const int w = blockIdx.x / 6;
    const int n0 = (blockIdx.x % 6) * BN;
    const int m0 = blockIdx.y * BM;
    const int wm = warp & 1, wn = warp >> 1;

    const float* W = (w == 0 ? Wq : w == 1 ? Wk : w == 2 ? Wv : Ws);
    const float* bias = (w == 0 ? b0 : w == 1 ? b1 : w == 2 ? b2 : b3);
    float* out = (w == 0 ? o0 : w == 1 ? o1 : w == 2 ? o2 : o3);

    uint32_t smb = (uint32_t)__cvta_generic_to_shared(sm);

    float c[4][4][4];
#pragma unroll
    for (int mi = 0; mi < 4; mi++)
#pragma unroll
        for (int ni = 0; ni < 4; ni++)
#pragma unroll
            for (int r = 0; r < 4; r++) c[mi][ni][r] = 0.f;

    auto load_stage = [&](int slot, int kt) {
        int k0 = kt * BK;
        uint32_t AsB = smb + (uint32_t)(slot * STAGE_FLOATS) * 4u;
        uint32_t BsB = AsB + AS_FLOATS * 4u;
#pragma unroll
        for (int s = 0; s < 4; s++) {
            int i = t + s * 256;
            int row = i >> 3, c4 = (i & 7) * 4;
            int grow = m0 + row;
            const float* src = A + (size_t)(grow < NN ? grow : 0) * DD + k0 + c4;
            cp16(AsB + (uint32_t)(row * SA + c4) * 4u, src);
        }
#pragma unroll
        for (int s = 0; s < 4; s++) {
            int i = t + s * 256;
            int row = i >> 5, c4 = (i & 31) * 4;
            const float* src = W + (size_t)(k0 + row) * DD + n0 + c4;
            cp16(BsB + (uint32_t)(row * SB + c4) * 4u, src);
        }
    };

#pragma unroll
    for (int s = 0; s < GSTAGES; s++) {
        load_stage(s, s);
        cp_commit();
    }

    for (int kt = 0; kt < NKT; kt++) {
        cp_wait2();
        __syncthreads();
        const float* As = sm + (kt % GSTAGES) * STAGE_FLOATS;
        const float* Bs = As + AS_FLOATS;
#pragma unroll
        for (int ks = 0; ks < 4; ks++) {
            int k0s = ks * 8;
            uint32_t a[4][4], b[4][2];
#pragma unroll
            for (int mi = 0; mi < 4; mi++) {
                int mrow = wm * 64 + mi * 16 + g;
                const float* p = As + mrow * SA + k0s + qd;
                a[mi][0] = f2tf32(p[0]);
                a[mi][1] = f2tf32(p[8 * SA]);
                a[mi][2] = f2tf32(p[4]);
                a[mi][3] = f2tf32(p[8 * SA + 4]);
            }
#pragma unroll
            for (int ni = 0; ni < 4; ni++) {
                int ncol = wn * 32 + ni * 8 + g;
                const float* p = Bs + (k0s + qd) * SB + ncol;
                b[ni][0] = f2tf32(p[0]);
                b[ni][1] = f2tf32(p[4 * SB]);
            }
#pragma unroll
            for (int mi = 0; mi < 4; mi++)
#pragma unroll
                for (int ni = 0; ni < 4; ni++) mma_tf32(c[mi][ni], a[mi], b[ni]);
        }
        __syncthreads();
        if (kt + GSTAGES < NKT) load_stage(kt % GSTAGES, kt + GSTAGES);
        cp_commit();
    }

#pragma unroll
    for (int mi = 0; mi < 4; mi++) {
#pragma unroll
        for (int rh = 0; rh < 2; rh++) {
            int grow = m0 + wm * 64 + mi * 16 + rh * 8 + g;
            if (grow >= NN) continue;
            float* orow = out + (size_t)grow * DD + n0;
#pragma unroll
            for (int ni = 0; ni < 4; ni++) {
                int col = wn * 32 + ni * 8 + 2 * qd;
                float2 val;
                val.x = c[mi][ni][rh * 2 + 0] + bias[n0 + col];
                val.y = c[mi][ni][rh * 2 + 1] + bias[n0 + col + 1];
                *(float2*)(orow + col) = val;
            }
        }
    }
}

// ================= P[n, h*16+i] = sum_c q[n, h*C+c] * We[i, h*C+c] =================
__global__ void p_kernel(const float* __restrict__ q, const float* __restrict__ We,
                         float* __restrict__ P) {
    __shared__ float qs[4][DD];
    int nb = blockIdx.x * 4;
    for (int idx = threadIdx.x; idx < 4 * DD; idx += 256) {
        int nn = nb + idx / DD;
        qs[idx / DD][idx % DD] = (nn < NN) ? q[(size_t)nn * DD + (idx % DD)] : 0.f;
    }
    __syncthreads();
    int local = threadIdx.x / 64;
    int t64 = threadIdx.x % 64;
    int n = nb + local;
    if (n >= NN) return;
    int h = t64 / EDIMF, i = t64 % EDIMF;
    const float* w = We + (size_t)i * DD + h * CC;
    const float* qq = qs[local] + h * CC;
    float s = 0.f;
#pragma unroll 8
    for (int c = 0; c < CC; c++) s = fmaf(qq[c], w[c], s);
    P[(size_t)n * (HH * EDIMF) + t64] = s;
}

// ================= alpha: warp per CSR edge, 4 heads x 8 lanes =================
__global__ void __launch_bounds__(256) alpha_kernel(
    const float* __restrict__ q, const float* __restrict__ kk,
    const float* __restrict__ P, const float* __restrict__ efc,
    const int* __restrict__ srcs, const int* __restrict__ dstc,
    float* __restrict__ alpha) {
    int e = blockIdx.x * 8 + (threadIdx.x >> 5);
    if (e >= EE) return;
    int lane = threadIdx.x & 31;
    int lg = lane & 7, h = lane >> 3;
    int src = srcs[e], dst = dstc[e];
    const float2* kr = (const float2*)(kk + (size_t)src * DD + h * CC);
    const float2* qr = (const float2*)(q + (size_t)dst * DD + h * CC);
    float s = 0.f;
#pragma unroll
    for (int j = 0; j < 12; j++) {
        float2 qv = qr[lg + 8 * j];
        float2 kv = kr[lg + 8 * j];
        s = fmaf(qv.x, kv.x, s);
        s = fmaf(qv.y, kv.y, s);
    }
    // fold ef·P partials into lane sums (i = lg and lg+8)
    const float* pp = P + (size_t)dst * (HH * EDIMF) + h * EDIMF;
    const float* ee = efc + (size_t)e * EDIMF;
    s = fmaf(ee[lg], pp[lg], s);
    s = fmaf(ee[lg + 8], pp[lg + 8], s);
    s += __shfl_xor_sync(0xffffffffu, s, 1);
    s += __shfl_xor_sync(0xffffffffu, s, 2);
    s += __shfl_xor_sync(0xffffffffu, s, 4);
    if (lg == 0) alpha[(size_t)e * HH + h] = s * 0.07216878364870322f;
}

// ================= aggregation: warp per node, fused softmax + message + epilogue =================
__global__ void __launch_bounds__(256) agg_kernel(
    const float* __restrict__ v, const float* __restrict__ skip,
    const float* __restrict__ efc, const float* __restrict__ alpha,
    const int* __restrict__ rowptr, const int* __restrict__ srcs,
    const float* __restrict__ We, float* __restrict__ out, int gelu) {
    __shared__ float wbuf[8][32 * HH];
    __shared__ float Ssm[8][2 * 32];
    int wid = threadIdx.x >> 5, lane = threadIdx.x & 31;
    int n = blockIdx.x * 8 + wid;
    if (n >= NN) return;
    int start = rowptr[n], end = rowptr[n + 1];

    // pass 1: per-head max
    float m0 = -1e30f, m1 = -1e30f, m2 = -1e30f, m3 = -1e30f;
    for (int e = start + lane; e < end; e += 32) {
        float4 a4 = *(const float4*)(alpha + (size_t)e * HH);
        m0 = fmaxf(m0, a4.x); m1 = fmaxf(m1, a4.y);
        m2 = fmaxf(m2, a4.z); m3 = fmaxf(m3, a4.w);
    }
#pragma unroll
    for (int o = 16; o > 0; o >>= 1) {
        m0 = fmaxf(m0, __shfl_xor_sync(0xffffffffu, m0, o));
        m1 = fmaxf(m1, __shfl_xor_sync(0xffffffffu, m1, o));
        m2 = fmaxf(m2, __shfl_xor_sync(0xffffffffu, m2, o));
        m3 = fmaxf(m3, __shfl_xor_sync(0xffffffffu, m3, o));
    }
    // pass 2: exp-sum
    float s0 = 0.f, s1 = 0.f, s2 = 0.f, s3 = 0.f;
    for (int e = start + lane; e < end; e += 32) {
        float4 a4 = *(const float4*)(alpha + (size_t)e * HH);
        s0 += expf(a4.x - m0); s1 += expf(a4.y - m1);
        s2 += expf(a4.z - m2); s3 += expf(a4.w - m3);
    }
#pragma unroll
    for (int o = 16; o > 0; o >>= 1) {
        s0 += __shfl_xor_sync(0xffffffffu, s0, o);
        s1 += __shfl_xor_sync(0xffffffffu, s1, o);
        s2 += __shfl_xor_sync(0xffffffffu, s2, o);
        s3 += __shfl_xor_sync(0xffffffffu, s3, o);
    }
    float i0 = 1.f / (s0 + 1e-16f), i1 = 1.f / (s1 + 1e-16f);
    float i2 = 1.f / (s2 + 1e-16f), i3 = 1.f / (s3 + 1e-16f);

    // pass 3: aggregate in chunks of 32 edges
    float acc[24];
#pragma unroll
    for (int j = 0; j < 24; j++) acc[j] = 0.f;
    float sa = 0.f, sb = 0.f;             // S entries: idx=lane (h=lane/16), idx=lane+32 (h=2+lane/16)
    int iA = lane & 15;
    int hA = lane >> 4, hB = 2 + (lane >> 4);
    for (int base = start; base < end; base += 32) {
        int e = base + lane;
        if (e < end) {
            float4 a4 = *(const float4*)(alpha + (size_t)e * HH);
            float4 w4;
            w4.x = expf(a4.x - m0) * i0;
            w4.y = expf(a4.y - m1) * i1;
            w4.z = expf(a4.z - m2) * i2;
            w4.w = expf(a4.w - m3) * i3;
            *(float4*)&wbuf[wid][lane * 4] = w4;
        }
        __syncwarp();
        int cnt = min(32, end - base);
        for (int ec = 0; ec < cnt; ec++) {
            int e2 = base + ec;
            int src = srcs[e2];
            const float* vr = v + (size_t)src * DD;
            float w0 = wbuf[wid][ec * 4 + 0];
            float w1 = wbuf[wid][ec * 4 + 1];
            float w2 = wbuf[wid][ec * 4 + 2];
            float w3 = wbuf[wid][ec * 4 + 3];
#pragma unroll
            for (int j = 0; j < 24; j++) {
                float wj = (j < 6) ? w0 : (j < 12) ? w1 : (j < 18) ? w2 : w3;
                acc[j] = fmaf(wj, vr[lane + 32 * j], acc[j]);
            }
            float efA = efc[(size_t)e2 * EDIMF + iA];
            sa = fmaf(wbuf[wid][ec * 4 + hA], efA, sa);
            sb = fmaf(wbuf[wid][ec * 4 + hB], efA, sb);
        }
        __syncwarp();
    }
    Ssm[wid][lane] = sa;
    Ssm[wid][lane + 32] = sb;
    __syncwarp();

    // epilogue: out = msg + S@We + skip (+ gelu)
    const float* sk = skip + (size_t)n * DD;
    float* orow = out + (size_t)n * DD;
#pragma unroll
    for (int j = 0; j < 24; j++) {
        int c = lane + 32 * j;
        int h = j / 6;
        float val = acc[j];
#pragma unroll
        for (int i = 0; i < 16; i++)
            val = fmaf(Ssm[wid][h * 16 + i], We[(size_t)i * DD + c], val);
        val += sk[c];
        if (gelu) val = 0.5f * val * (1.f + erff(val * 0.7071067811865475f));
        orow[c] = val;
    }
}

// ================= layernorm + global mean pool =================
__global__ void ln_pool_kernel(const float* __restrict__ h, float* __restrict__ out) {
    __shared__ float red[256];
    int t = threadIdx.x;
    float acc0 = 0.f, acc1 = 0.f, acc2 = 0.f;
    for (int n = blockIdx.x; n < NN; n += gridDim.x) {
        const float* row = h + (size_t)n * DD;
        float v0 = row[t], v1 = row[t + 256], v2 = row[t + 512];
        red[t] = v0 + v1 + v2;
        __syncthreads();
        for (int off = 128; off > 0; off >>= 1) {
            if (t < off) red[t] += red[t + off];
            __syncthreads();
        }
        float mu = red[0] * (1.f / DD);
        __syncthreads();
        float d0 = v0 - mu, d1 = v1 - mu, d2 = v2 - mu;
        red[t] = d0 * d0 + d1 * d1 + d2 * d2;
        __syncthreads();
        for (int off = 128; off > 0; off >>= 1) {
            if (t < off) red[t] += red[t + off];
            __syncthreads();
        }
        float rstd = rsqrtf(red[0] * (1.f / DD) + 1e-5f);
        __syncthreads();
        acc0 += d0 * rstd;
        acc1 += d1 * rstd;
        acc2 += d2 * rstd;
    }
    atomicAdd(&out[t], acc0);
    atomicAdd(&out[t + 256], acc1);
    atomicAdd(&out[t + 512], acc2);
}

__global__ void ln_final_kernel(float* __restrict__ out, const float* __restrict__ g,
                                const float* __restrict__ b) {
    int c = threadIdx.x + blockIdx.x * blockDim.x;
    if (c < DD) out[c] = out[c] * g[c] * (1.f / NN) + b[c];
}

// ================= launch =================
extern "C" void kernel_launch(void* const* d_in, const int* in_sizes, int n_in,
                              void* d_out, int out_size) {
    const float* x          = (const float*)d_in[0];
    const float* edge_attr  = (const float*)d_in[1];
    const int*   edge_index = (const int*)d_in[2];
    const float* rel_emb    = (const float*)d_in[3];
    const float* W_edge     = (const float*)d_in[4];
    const float* b_edge     = (const float*)d_in[5];
    const float* Wk         = (const float*)d_in[6];
    const float* bk         = (const float*)d_in[7];
    const float* Wq         = (const float*)d_in[8];
    const float* bq         = (const float*)d_in[9];
    const float* Wv         = (const float*)d_in[10];
    const float* bv         = (const float*)d_in[11];
    const float* We         = (const float*)d_in[12];
    const float* Wskip      = (const float*)d_in[13];
    const float* bskip      = (const float*)d_in[14];
    const float* ln_g       = (const float*)d_in[15];
    const float* ln_b       = (const float*)d_in[16];
    float* out = (float*)d_out;

    float *bufA, *bufB, *q, *k, *v, *skip, *ef, *efc, *alpha, *P;
    int *rowptr, *cnt, *cur, *srcidx, *dstc;
    cudaGetSymbolAddress((void**)&bufA, g_bufA);
    cudaGetSymbolAddress((void**)&bufB, g_bufB);
    cudaGetSymbolAddress((void**)&q, g_q);
    cudaGetSymbolAddress((void**)&k, g_k);
    cudaGetSymbolAddress((void**)&v, g_v);
    cudaGetSymbolAddress((void**)&skip, g_skip);
    cudaGetSymbolAddress((void**)&ef, g_ef);
    cudaGetSymbolAddress((void**)&efc, g_efcsr);
    cudaGetSymbolAddress((void**)&alpha, g_alpha);
    cudaGetSymbolAddress((void**)&P, g_P);
    cudaGetSymbolAddress((void**)&rowptr, g_rowptr);
    cudaGetSymbolAddress((void**)&cnt, g_cnt);
    cudaGetSymbolAddress((void**)&cur, g_cur);
    cudaGetSymbolAddress((void**)&srcidx, g_srcidx);
    cudaGetSymbolAddress((void**)&dstc, g_dstc);

    cudaFuncSetAttribute(gemm4_kernel, cudaFuncAttributeMaxDynamicSharedMemorySize, GEMM_SMEM);

    cudaMemsetAsync(cnt, 0, NN * sizeof(int));
    cudaMemsetAsync(cur, 0, NN * sizeof(int));
    // kernels 1-3; gemm4(L0) is kernel #4 = ncu capture slot
    ef_kernel<<<(EE + 255) / 256, 256>>>(edge_attr, rel_emb, W_edge, b_edge, ef);
    count_kernel<<<(EE + 255) / 256, 256>>>(edge_index, cnt);
    scan_kernel<<<1, 1024>>>(cnt, rowptr);

    const float* hin = x;
    for (int l = 0; l < LL; l++) {
        const float* We_l = We + (size_t)l * EDIMF * DD;
        gemm4_kernel<<<dim3(24, (NN + BM - 1) / BM), 256, GEMM_SMEM>>>(
            hin,
            Wq + (size_t)l * DD * DD, Wk + (size_t)l * DD * DD,
            Wv + (size_t)l * DD * DD, Wskip + (size_t)l * DD * DD,
            bq + (size_t)l * DD, bk + (size_t)l * DD, bv + (size_t)l * DD, bskip + (size_t)l * DD,
            q, k, v, skip);
        if (l == 0)
            scatter_kernel<<<(EE + 255) / 256, 256>>>(edge_index, rowptr, cur, srcidx, dstc, ef, efc);
        p_kernel<<<(NN + 3) / 4, 256>>>(q, We_l, P);
        alpha_kernel<<<(EE + 7) / 8, 256>>>(q, k, P, efc, srcidx, dstc, alpha);
        float* hout = (l & 1) ? bufB : bufA;
        agg_kernel<<<(NN + 7) / 8, 256>>>(v, skip, efc, alpha, rowptr, srcidx, We_l, hout,
                                          (l < LL - 1) ? 1 : 0);
        hin = hout;
    }

    cudaMemsetAsync(out, 0, DD * sizeof(float));
    ln_pool_kernel<<<1024, 256>>>(hin, out);
    ln_final_kernel<<<3, 256>>>(out, ln_g, ln_b);
}

// round 7
// speedup vs baseline: 1.3747x; 1.0025x over previous
#include <cuda_runtime.h>
#include <cstdint>

#define NN 10000
#define EE 100000
#define DD 768
#define HH 4
#define CC 192
#define LL 3
#define EDIMF 16
#define NRELC 10

// GEMM tiling: block 128x128, 8 warps as 2(m) x 4(n), warp tile 64x32
#define BM 128
#define BN 128
#define BK 32
#define NKT (DD / BK)
#define GSTAGES 3
#define SA 36
#define SB 136
#define AS_FLOATS (BM * SA)
#define BS_FLOATS (BK * SB)
#define STAGE_FLOATS (AS_FLOATS + BS_FLOATS)
#define GEMM_SMEM (GSTAGES * STAGE_FLOATS * 4)   // ~105 KB -> 2 CTA/SM

#define WDEG 64   // per-warp smem alpha capacity (fast path)

// ---------------- scratch (static device globals; no allocation) ----------------
__device__ float g_bufA[NN * DD];
__device__ float g_bufB[NN * DD];
__device__ float g_q[NN * DD];
__device__ float g_k[NN * DD];
__device__ float g_v[NN * DD];
__device__ float g_skip[NN * DD];
__device__ float g_ef[EE * EDIMF];
__device__ float g_efcsr[EE * EDIMF];
__device__ float g_alpha[EE * HH];     // fallback only (deg > WDEG)
__device__ float g_P[NN * HH * EDIMF];
__device__ int   g_rowptr[NN + 1];
__device__ int   g_cnt[NN];
__device__ int   g_cur[NN];
__device__ int   g_srcidx[EE];

// ---------------- async copy helpers ----------------
__device__ __forceinline__ void cp16(uint32_t dst, const float* src) {
    asm volatile("cp.async.cg.shared.global [%0], [%1], 16;" ::"r"(dst),
                 "l"(__cvta_generic_to_global(src)));
}
__device__ __forceinline__ void cp_commit() { asm volatile("cp.async.commit_group;"); }
__device__ __forceinline__ void cp_wait2() { asm volatile("cp.async.wait_group 2;"); }

__device__ __forceinline__ uint32_t f2tf32(float f) {
    uint32_t u;
    asm("cvt.rna.tf32.f32 %0, %1;" : "=r"(u) : "f"(f));
    return u;
}

__device__ __forceinline__ void mma_tf32(float* c, const uint32_t* a, const uint32_t* b) {
    asm volatile(
        "mma.sync.aligned.m16n8k8.row.col.f32.tf32.tf32.f32 "
        "{%0,%1,%2,%3}, {%4,%5,%6,%7}, {%8,%9}, {%0,%1,%2,%3};"
        : "+f"(c[0]), "+f"(c[1]), "+f"(c[2]), "+f"(c[3])
        : "r"(a[0]), "r"(a[1]), "r"(a[2]), "r"(a[3]), "r"(b[0]), "r"(b[1]));
}

// ================= edge feature projection =================
__global__ void ef_kernel(const float* __restrict__ edge_attr, const float* __restrict__ rel_emb,
                          const float* __restrict__ W_edge, const float* __restrict__ b_edge,
                          float* __restrict__ ef) {
    __shared__ float sW[EDIMF * EDIMF];
    __shared__ float sB[EDIMF];
    __shared__ float sR[NRELC * (EDIMF - 1)];
    int t = threadIdx.x;
    if (t < EDIMF * EDIMF) sW[t] = W_edge[t];
    if (t < EDIMF) sB[t] = b_edge[t];
    if (t < NRELC * (EDIMF - 1)) sR[t] = rel_emb[t];
    __syncthreads();
    int e = blockIdx.x * blockDim.x + t;
    if (e >= EE) return;
    int r = (int)edge_attr[2 * e];
    r = min(max(r, 0), NRELC - 1);
    float feat[EDIMF];
#pragma unroll
    for (int i = 0; i < EDIMF - 1; i++) feat[i] = sR[r * (EDIMF - 1) + i];
    feat[EDIMF - 1] = edge_attr[2 * e + 1];
#pragma unroll
    for (int j = 0; j < EDIMF; j++) {
        float s = sB[j];
#pragma unroll
        for (int i = 0; i < EDIMF; i++) s += feat[i] * sW[i * EDIMF + j];
        ef[(size_t)e * EDIMF + j] = s;
    }
}

// ================= CSR build =================
__global__ void count_kernel(const int* __restrict__ edge_index, int* __restrict__ cnt) {
    int e = blockIdx.x * blockDim.x + threadIdx.x;
    if (e < EE) atomicAdd(&cnt[edge_index[EE + e]], 1);
}

__global__ void scan_kernel(const int* __restrict__ cnt, int* __restrict__ rowptr) {
    __shared__ int s[1024];
    int t = threadIdx.x;
    int carry = 0;
    if (t == 0) rowptr[0] = 0;
    for (int base = 0; base < NN; base += 1024) {
        int i = base + t;
        s[t] = (i < NN) ? cnt[i] : 0;
        __syncthreads();
        for (int off = 1; off < 1024; off <<= 1) {
            int add = (t >= off) ? s[t - off] : 0;
            __syncthreads();
            s[t] += add;
            __syncthreads();
        }
        if (i < NN) rowptr[i + 1] = carry + s[t];
        int tot = s[1023];
        __syncthreads();
        carry += tot;
    }
}

__global__ void scatter_kernel(const int* __restrict__ edge_index, const int* __restrict__ rowptr,
                               int* __restrict__ cur, int* __restrict__ srcs,
                               const float* __restrict__ ef, float* __restrict__ efc) {
    int e = blockIdx.x * blockDim.x + threadIdx.x;
    if (e >= EE) return;
    int dst = edge_index[EE + e];
    int pos = rowptr[dst] + atomicAdd(&cur[dst], 1);
    srcs[pos] = edge_index[e];
    const float4* s = (const float4*)(ef + (size_t)e * EDIMF);
    float4* d = (float4*)(efc + (size_t)pos * EDIMF);
    d[0] = s[0]; d[1] = s[1]; d[2] = s[2]; d[3] = s[3];
}

// ================= fused QKVS GEMM via mma.sync tf32 =================
__global__ void __launch_bounds__(256, 2) gemm4_kernel(
    const float* __restrict__ A,
    const float* __restrict__ Wq, const float* __restrict__ Wk,
    const float* __restrict__ Wv, const float* __restrict__ Ws,
    const float* __restrict__ b0, const float* __restrict__ b1,
    const float* __restrict__ b2, const float* __restrict__ b3,
    float* __restrict__ o0, float* __restrict__ o1,
    float* __restrict__ o2, float* __restrict__ o3) {
    extern __shared__ float sm[];
    const int t = threadIdx.x;
    const int warp = t >> 5, lane = t & 31;
    const int g = lane >> 2, qd = lane & 3;
    const int w = blockIdx.x / 6;
    const int n0 = (blockIdx.x % 6) * BN;
    const int m0 = blockIdx.y * BM;
    const int wm = warp & 1, wn = warp >> 1;

    const float* W = (w == 0 ? Wq : w == 1 ? Wk : w == 2 ? Wv : Ws);
    const float* bias = (w == 0 ? b0 : w == 1 ? b1 : w == 2 ? b2 : b3);
    float* out = (w == 0 ? o0 : w == 1 ? o1 : w == 2 ? o2 : o3);

    uint32_t smb = (uint32_t)__cvta_generic_to_shared(sm);

    float c[4][4][4];
#pragma unroll
    for (int mi = 0; mi < 4; mi++)
#pragma unroll
        for (int ni = 0; ni < 4; ni++)
#pragma unroll
            for (int r = 0; r < 4; r++) c[mi][ni][r] = 0.f;

    auto load_stage = [&](int slot, int kt) {
        int k0 = kt * BK;
        uint32_t AsB = smb + (uint32_t)(slot * STAGE_FLOATS) * 4u;
        uint32_t BsB = AsB + AS_FLOATS * 4u;
#pragma unroll
        for (int s = 0; s < 4; s++) {
            int i = t + s * 256;
            int row = i >> 3, c4 = (i & 7) * 4;
            int grow = m0 + row;
            const float* src = A + (size_t)(grow < NN ? grow : 0) * DD + k0 + c4;
            cp16(AsB + (uint32_t)(row * SA + c4) * 4u, src);
        }
#pragma unroll
        for (int s = 0; s < 4; s++) {
            int i = t + s * 256;
            int row = i >> 5, c4 = (i & 31) * 4;
            const float* src = W + (size_t)(k0 + row) * DD + n0 + c4;
            cp16(BsB + (uint32_t)(row * SB + c4) * 4u, src);
        }
    };

#pragma unroll
    for (int s = 0; s < GSTAGES; s++) {
        load_stage(s, s);
        cp_commit();
    }

    for (int kt = 0; kt < NKT; kt++) {
        cp_wait2();
        __syncthreads();
        const float* As = sm + (kt % GSTAGES) * STAGE_FLOATS;
        const float* Bs = As + AS_FLOATS;
#pragma unroll
        for (int ks = 0; ks < 4; ks++) {
            int k0s = ks * 8;
            uint32_t a[4][4], b[4][2];
#pragma unroll
            for (int mi = 0; mi < 4; mi++) {
                int mrow = wm * 64 + mi * 16 + g;
                const float* p = As + mrow * SA + k0s + qd;
                a[mi][0] = f2tf32(p[0]);
                a[mi][1] = f2tf32(p[8 * SA]);
                a[mi][2] = f2tf32(p[4]);
                a[mi][3] = f2tf32(p[8 * SA + 4]);
            }
#pragma unroll
            for (int ni = 0; ni < 4; ni++) {
                int ncol = wn * 32 + ni * 8 + g;
                const float* p = Bs + (k0s + qd) * SB + ncol;
                b[ni][0] = f2tf32(p[0]);
                b[ni][1] = f2tf32(p[4 * SB]);
            }
#pragma unroll
            for (int mi = 0; mi < 4; mi++)
#pragma unroll
                for (int ni = 0; ni < 4; ni++) mma_tf32(c[mi][ni], a[mi], b[ni]);
        }
        __syncthreads();
        if (kt + GSTAGES < NKT) load_stage(kt % GSTAGES, kt + GSTAGES);
        cp_commit();
    }

#pragma unroll
    for (int mi = 0; mi < 4; mi++) {
#pragma unroll
        for (int rh = 0; rh < 2; rh++) {
            int grow = m0 + wm * 64 + mi * 16 + rh * 8 + g;
            if (grow >= NN) continue;
            float* orow = out + (size_t)grow * DD + n0;
#pragma unroll
            for (int ni = 0; ni < 4; ni++) {
                int col = wn * 32 + ni * 8 + 2 * qd;
                float2 val;
                val.x = c[mi][ni][rh * 2 + 0] + bias[n0 + col];
                val.y = c[mi][ni][rh * 2 + 1] + bias[n0 + col + 1];
                *(float2*)(orow + col) = val;
            }
        }
    }
}

// ================= P[n, h*16+i] = sum_c q[n, h*C+c] * We[i, h*C+c] =================
__global__ void p_kernel(const float* __restrict__ q, const float* __restrict__ We,
                         float* __restrict__ P) {
    __shared__ float qs[4][DD];
    int nb = blockIdx.x * 4;
    for (int idx = threadIdx.x; idx < 4 * DD; idx += 256) {
        int nn = nb + idx / DD;
        qs[idx / DD][idx % DD] = (nn < NN) ? q[(size_t)nn * DD + (idx % DD)] : 0.f;
    }
    __syncthreads();
    int local = threadIdx.x / 64;
    int t64 = threadIdx.x % 64;
    int n = nb + local;
    if (n >= NN) return;
    int h = t64 / EDIMF, i = t64 % EDIMF;
    const float* w = We + (size_t)i * DD + h * CC;
    const float* qq = qs[local] + h * CC;
    float s = 0.f;
#pragma unroll 8
    for (int c = 0; c < CC; c++) s = fmaf(qq[c], w[c], s);
    P[(size_t)n * (HH * EDIMF) + t64] = s;
}

// ================= fused attention: warp per node (alpha + softmax + aggregate) =================
__global__ void __launch_bounds__(256) node_fused_kernel(
    const float* __restrict__ q, const float* __restrict__ kk, const float* __restrict__ v,
    const float* __restrict__ skip, const float* __restrict__ efc, const float* __restrict__ P,
    const int* __restrict__ rowptr, const int* __restrict__ srcs,
    const float* __restrict__ We, float* __restrict__ galpha,
    float* __restrict__ out, int gelu) {
    __shared__ float abuf[8][WDEG * HH];
    __shared__ float Ssm[8][2 * 32];
    const int wid = threadIdx.x >> 5, lane = threadIdx.x & 31;
    const int n = blockIdx.x * 8 + wid;
    if (n >= NN) return;
    const int start = rowptr[n], end = rowptr[n + 1];
    const int deg = end - start;
    const unsigned FULL = 0xffffffffu;
    const int h = lane >> 3, lg = lane & 7;   // alpha layout: 4 heads x 8 lanes

    // weight storage: smem fast path, global fallback
    float* wp = (deg <= WDEG) ? abuf[wid] : (galpha + (size_t)start * HH);

    // stage q row in alpha layout (24 floats/lane)
    const float2* qr = (const float2*)(q + (size_t)n * DD + h * CC);
    float2 qv[12];
#pragma unroll
    for (int j = 0; j < 12; j++) qv[j] = qr[lg + 8 * j];
    // P entries for this lane's positions
    const float p0 = P[(size_t)n * (HH * EDIMF) + h * EDIMF + lg];
    const float p1 = P[(size_t)n * (HH * EDIMF) + h * EDIMF + lg + 8];

    // ---- pass A: alphas ----
    for (int base = 0; base < deg; base += 32) {
        int cnt = min(32, deg - base);
        int srcReg = (base + lane < deg) ? srcs[start + base + lane] : 0;
        for (int i = 0; i < cnt; i++) {
            int src = __shfl_sync(FULL, srcReg, i);
            int e = start + base + i;
            const float2* kr = (const float2*)(kk + (size_t)src * DD + h * CC);
            float s = 0.f;
#pragma unroll
            for (int j = 0; j < 12; j++) {
                float2 kv = kr[lg + 8 * j];
                s = fmaf(qv[j].x, kv.x, s);
                s = fmaf(qv[j].y, kv.y, s);
            }
            s = fmaf(efc[(size_t)e * EDIMF + lg], p0, s);
            s = fmaf(efc[(size_t)e * EDIMF + lg + 8], p1, s);
            s += __shfl_xor_sync(FULL, s, 1);
            s += __shfl_xor_sync(FULL, s, 2);
            s += __shfl_xor_sync(FULL, s, 4);
            if (lg == 0) wp[(base + i) * HH + h] = s * 0.07216878364870322f;
        }
    }
    __syncwarp();

    // ---- softmax per head (lanes 0..3, deg ~10 so serial is cheap) ----
    if (lane < HH) {
        float m = -1e30f;
        for (int i = 0; i < deg; i++) m = fmaxf(m, wp[i * HH + lane]);
        float ssum = 0.f;
        for (int i = 0; i < deg; i++) {
            float wv = expf(wp[i * HH + lane] - m);
            wp[i * HH + lane] = wv;
            ssum += wv;
        }
        float inv = 1.f / (ssum + 1e-16f);
        for (int i = 0; i < deg; i++) wp[i * HH + lane] *= inv;
    }
    __syncwarp();

    // ---- pass B: aggregate ----
    float acc[24];
#pragma unroll
    for (int j = 0; j < 24; j++) acc[j] = 0.f;
    float sa = 0.f, sb = 0.f;
    const int iA = lane & 15;
    const int hA = lane >> 4, hB = 2 + (lane >> 4);
    for (int base = 0; base < deg; base += 32) {
        int cnt = min(32, deg - base);
        int srcReg = (base + lane < deg) ? srcs[start + base + lane] : 0;
        for (int i = 0; i < cnt; i++) {
            int src = __shfl_sync(FULL, srcReg, i);
            int idx = base + i;
            const float* vr = v + (size_t)src * DD;
            float w0 = wp[idx * HH + 0];
            float w1 = wp[idx * HH + 1];
            float w2 = wp[idx * HH + 2];
            float w3 = wp[idx * HH + 3];
#pragma unroll
            for (int j = 0; j < 24; j++) {
                float wj = (j < 6) ? w0 : (j < 12) ? w1 : (j < 18) ? w2 : w3;
                acc[j] = fmaf(wj, vr[lane + 32 * j], acc[j]);
            }
            float efA = efc[(size_t)(start + idx) * EDIMF + iA];
            sa = fmaf(wp[idx * HH + hA], efA, sa);
            sb = fmaf(wp[idx * HH + hB], efA, sb);
        }
    }
    Ssm[wid][lane] = sa;
    Ssm[wid][lane + 32] = sb;
    __syncwarp();

    // ---- epilogue: out = msg + S@We + skip (+ gelu) ----
    const float* sk = skip + (size_t)n * DD;
    float* orow = out + (size_t)n * DD;
#pragma unroll
    for (int j = 0; j < 24; j++) {
        int c = lane + 32 * j;
        int hh = j / 6;
        float val = acc[j];
#pragma unroll
        for (int i = 0; i < 16; i++)
            val = fmaf(Ssm[wid][hh * 16 + i], We[(size_t)i * DD + c], val);
        val += sk[c];
        if (gelu) val = 0.5f * val * (1.f + erff(val * 0.7071067811865475f));
        orow[c] = val;
    }
}

// ================= layernorm + global mean pool =================
__global__ void ln_pool_kernel(const float* __restrict__ h, float* __restrict__ out) {
    __shared__ float red[256];
    int t = threadIdx.x;
    float acc0 = 0.f, acc1 = 0.f, acc2 = 0.f;
    for (int n = blockIdx.x; n < NN; n += gridDim.x) {
        const float* row = h + (size_t)n * DD;
        float v0 = row[t], v1 = row[t + 256], v2 = row[t + 512];
        red[t] = v0 + v1 + v2;
        __syncthreads();
        for (int off = 128; off > 0; off >>= 1) {
            if (t < off) red[t] += red[t + off];
            __syncthreads();
        }
        float mu = red[0] * (1.f / DD);
        __syncthreads();
        float d0 = v0 - mu, d1 = v1 - mu, d2 = v2 - mu;
        red[t] = d0 * d0 + d1 * d1 + d2 * d2;
        __syncthreads();
        for (int off = 128; off > 0; off >>= 1) {
            if (t < off) red[t] += red[t + off];
            __syncthreads();
        }
        float rstd = rsqrtf(red[0] * (1.f / DD) + 1e-5f);
        __syncthreads();
        acc0 += d0 * rstd;
        acc1 += d1 * rstd;
        acc2 += d2 * rstd;
    }
    atomicAdd(&out[t], acc0);
    atomicAdd(&out[t + 256], acc1);
    atomicAdd(&out[t + 512], acc2);
}

__global__ void ln_final_kernel(float* __restrict__ out, const float* __restrict__ g,
                                const float* __restrict__ b) {
    int c = threadIdx.x + blockIdx.x * blockDim.x;
    if (c < DD) out[c] = out[c] * g[c] * (1.f / NN) + b[c];
}

// ================= launch =================
extern "C" void kernel_launch(void* const* d_in, const int* in_sizes, int n_in,
                              void* d_out, int out_size) {
    const float* x          = (const float*)d_in[0];
    const float* edge_attr  = (const float*)d_in[1];
    const int*   edge_index = (const int*)d_in[2];
    const float* rel_emb    = (const float*)d_in[3];
    const float* W_edge     = (const float*)d_in[4];
    const float* b_edge     = (const float*)d_in[5];
    const float* Wk         = (const float*)d_in[6];
    const float* bk         = (const float*)d_in[7];
    const float* Wq         = (const float*)d_in[8];
    const float* bq         = (const float*)d_in[9];
    const float* Wv         = (const float*)d_in[10];
    const float* bv         = (const float*)d_in[11];
    const float* We         = (const float*)d_in[12];
    const float* Wskip      = (const float*)d_in[13];
    const float* bskip      = (const float*)d_in[14];
    const float* ln_g       = (const float*)d_in[15];
    const float* ln_b       = (const float*)d_in[16];
    float* out = (float*)d_out;

    float *bufA, *bufB, *q, *k, *v, *skip, *ef, *efc, *alpha, *P;
    int *rowptr, *cnt, *cur, *srcidx;
    cudaGetSymbolAddress((void**)&bufA, g_bufA);
    cudaGetSymbolAddress((void**)&bufB, g_bufB);
    cudaGetSymbolAddress((void**)&q, g_q);
    cudaGetSymbolAddress((void**)&k, g_k);
    cudaGetSymbolAddress((void**)&v, g_v);
    cudaGetSymbolAddress((void**)&skip, g_skip);
    cudaGetSymbolAddress((void**)&ef, g_ef);
    cudaGetSymbolAddress((void**)&efc, g_efcsr);
    cudaGetSymbolAddress((void**)&alpha, g_alpha);
    cudaGetSymbolAddress((void**)&P, g_P);
    cudaGetSymbolAddress((void**)&rowptr, g_rowptr);
    cudaGetSymbolAddress((void**)&cnt, g_cnt);
    cudaGetSymbolAddress((void**)&cur, g_cur);
    cudaGetSymbolAddress((void**)&srcidx, g_srcidx);

    cudaFuncSetAttribute(gemm4_kernel, cudaFuncAttributeMaxDynamicSharedMemorySize, GEMM_SMEM);

    cudaMemsetAsync(cnt, 0, NN * sizeof(int));
    cudaMemsetAsync(cur, 0, NN * sizeof(int));
    // kernels 1-3; gemm4(L0) is kernel #4 = ncu capture slot
    ef_kernel<<<(EE + 255) / 256, 256>>>(edge_attr, rel_emb, W_edge, b_edge, ef);
    count_kernel<<<(EE + 255) / 256, 256>>>(edge_index, cnt);
    scan_kernel<<<1, 1024>>>(cnt, rowptr);

    const float* hin = x;
    for (int l = 0; l < LL; l++) {
        const float* We_l = We + (size_t)l * EDIMF * DD;
        gemm4_kernel<<<dim3(24, (NN + BM - 1) / BM), 256, GEMM_SMEM>>>(
            hin,
            Wq + (size_t)l * DD * DD, Wk + (size_t)l * DD * DD,
            Wv + (size_t)l * DD * DD, Wskip + (size_t)l * DD * DD,
            bq + (size_t)l * DD, bk + (size_t)l * DD, bv + (size_t)l * DD, bskip + (size_t)l * DD,
            q, k, v, skip);
        if (l == 0)
            scatter_kernel<<<(EE + 255) / 256, 256>>>(edge_index, rowptr, cur, srcidx, ef, efc);
        p_kernel<<<(NN + 3) / 4, 256>>>(q, We_l, P);
        float* hout = (l & 1) ? bufB : bufA;
        node_fused_kernel<<<(NN + 7) / 8, 256>>>(q, k, v, skip, efc, P, rowptr, srcidx, We_l,
                                                 alpha, hout, (l < LL - 1) ? 1 : 0);
        hin = hout;
    }

    cudaMemsetAsync(out, 0, DD * sizeof(float));
    ln_pool_kernel<<<1024, 256>>>(hin, out);
    ln_final_kernel<<<3, 256>>>(out, ln_g, ln_b);
}

// round 8
// speedup vs baseline: 2.2988x; 1.6723x over previous
#include <cuda_runtime.h>
#include <cstdint>

#define NN 10000
#define EE 100000
#define DD 768
#define HH 4
#define CC 192
#define LL 3
#define EDIMF 16
#define NRELC 10

// GEMM tiling: block 128x128, 8 warps as 2(m) x 4(n), warp tile 64x32
#define BM 128
#define BN 128
#define BK 32
#define NKT (DD / BK)
#define GSTAGES 3
#define SA 36
#define SB 136
#define AS_FLOATS (BM * SA)
#define BS_FLOATS (BK * SB)
#define STAGE_FLOATS (AS_FLOATS + BS_FLOATS)
#define GEMM_SMEM (GSTAGES * STAGE_FLOATS * 4)   // ~105 KB -> 2 CTA/SM

#define WDEG 64   // per-warp smem alpha capacity (fast path)

// ---------------- scratch (static device globals; no allocation) ----------------
__device__ float g_bufA[NN * DD];
__device__ float g_bufB[NN * DD];
__device__ float g_q[NN * DD];
__device__ float g_k[NN * DD];
__device__ float g_v[NN * DD];
__device__ float g_skip[NN * DD];
__device__ float g_ef[EE * EDIMF];
__device__ float g_efcsr[EE * EDIMF];
__device__ float g_alpha[EE * HH];     // fallback only (deg > WDEG)
__device__ float g_P[NN * HH * EDIMF];
__device__ float g_WeT[LL * DD * EDIMF];   // WeT[l][d*16+i] = We[l][i*DD+d]
__device__ int   g_rowptr[NN + 1];
__device__ int   g_cnt[NN];
__device__ int   g_cur[NN];
__device__ int   g_srcidx[EE];

// ---------------- async copy helpers ----------------
__device__ __forceinline__ void cp16(uint32_t dst, const float* src) {
    asm volatile("cp.async.cg.shared.global [%0], [%1], 16;" ::"r"(dst),
                 "l"(__cvta_generic_to_global(src)));
}
__device__ __forceinline__ void cp_commit() { asm volatile("cp.async.commit_group;"); }
__device__ __forceinline__ void cp_wait2() { asm volatile("cp.async.wait_group 2;"); }

__device__ __forceinline__ uint32_t f2tf32(float f) {
    uint32_t u;
    asm("cvt.rna.tf32.f32 %0, %1;" : "=r"(u) : "f"(f));
    return u;
}

__device__ __forceinline__ void mma_tf32(float* c, const uint32_t* a, const uint32_t* b) {
    asm volatile(
        "mma.sync.aligned.m16n8k8.row.col.f32.tf32.tf32.f32 "
        "{%0,%1,%2,%3}, {%4,%5,%6,%7}, {%8,%9}, {%0,%1,%2,%3};"
        : "+f"(c[0]), "+f"(c[1]), "+f"(c[2]), "+f"(c[3])
        : "r"(a[0]), "r"(a[1]), "r"(a[2]), "r"(a[3]), "r"(b[0]), "r"(b[1]));
}

// ================= prep1: edge count for CSR + build WeT for all layers =================
__global__ void prep1_kernel(const int* __restrict__ edge_index, int* __restrict__ cnt,
                             const float* __restrict__ We, float* __restrict__ WeT) {
    int idx = blockIdx.x * blockDim.x + threadIdx.x;
    if (idx < EE) atomicAdd(&cnt[edge_index[EE + idx]], 1);
    if (idx < LL * DD * EDIMF) {
        int l = idx / (DD * EDIMF);
        int rem = idx % (DD * EDIMF);
        int d = rem >> 4, i = rem & 15;
        WeT[idx] = We[(size_t)l * EDIMF * DD + (size_t)i * DD + d];
    }
}

// ================= edge feature projection =================
__global__ void ef_kernel(const float* __restrict__ edge_attr, const float* __restrict__ rel_emb,
                          const float* __restrict__ W_edge, const float* __restrict__ b_edge,
                          float* __restrict__ ef) {
    __shared__ float sW[EDIMF * EDIMF];
    __shared__ float sB[EDIMF];
    __shared__ float sR[NRELC * (EDIMF - 1)];
    int t = threadIdx.x;
    if (t < EDIMF * EDIMF) sW[t] = W_edge[t];
    if (t < EDIMF) sB[t] = b_edge[t];
    if (t < NRELC * (EDIMF - 1)) sR[t] = rel_emb[t];
    __syncthreads();
    int e = blockIdx.x * blockDim.x + t;
    if (e >= EE) return;
    int r = (int)edge_attr[2 * e];
    r = min(max(r, 0), NRELC - 1);
    float feat[EDIMF];
#pragma unroll
    for (int i = 0; i < EDIMF - 1; i++) feat[i] = sR[r * (EDIMF - 1) + i];
    feat[EDIMF - 1] = edge_attr[2 * e + 1];
#pragma unroll
    for (int j = 0; j < EDIMF; j++) {
        float s = sB[j];
#pragma unroll
        for (int i = 0; i < EDIMF; i++) s += feat[i] * sW[i * EDIMF + j];
        ef[(size_t)e * EDIMF + j] = s;
    }
}

// ================= CSR scan =================
__global__ void scan_kernel(const int* __restrict__ cnt, int* __restrict__ rowptr) {
    __shared__ int s[1024];
    int t = threadIdx.x;
    int carry = 0;
    if (t == 0) rowptr[0] = 0;
    for (int base = 0; base < NN; base += 1024) {
        int i = base + t;
        s[t] = (i < NN) ? cnt[i] : 0;
        __syncthreads();
        for (int off = 1; off < 1024; off <<= 1) {
            int add = (t >= off) ? s[t - off] : 0;
            __syncthreads();
            s[t] += add;
            __syncthreads();
        }
        if (i < NN) rowptr[i + 1] = carry + s[t];
        int tot = s[1023];
        __syncthreads();
        carry += tot;
    }
}

__global__ void scatter_kernel(const int* __restrict__ edge_index, const int* __restrict__ rowptr,
                               int* __restrict__ cur, int* __restrict__ srcs,
                               const float* __restrict__ ef, float* __restrict__ efc) {
    int e = blockIdx.x * blockDim.x + threadIdx.x;
    if (e >= EE) return;
    int dst = edge_index[EE + e];
    int pos = rowptr[dst] + atomicAdd(&cur[dst], 1);
    srcs[pos] = edge_index[e];
    const float4* s = (const float4*)(ef + (size_t)e * EDIMF);
    float4* d = (float4*)(efc + (size_t)pos * EDIMF);
    d[0] = s[0]; d[1] = s[1]; d[2] = s[2]; d[3] = s[3];
}

// ================= fused QKVS GEMM via mma.sync tf32 =================
__global__ void __launch_bounds__(256, 2) gemm4_kernel(
    const float* __restrict__ A,
    const float* __restrict__ Wq, const float* __restrict__ Wk,
    const float* __restrict__ Wv, const float* __restrict__ Ws,
    const float* __restrict__ b0, const float* __restrict__ b1,
    const float* __restrict__ b2, const float* __restrict__ b3,
    float* __restrict__ o0, float* __restrict__ o1,
    float* __restrict__ o2, float* __restrict__ o3) {
    extern __shared__ float sm[];
    const int t = threadIdx.x;
    const int warp = t >> 5, lane = t & 31;
    const int g = lane >> 2, qd = lane & 3;
    const int w = blockIdx.x / 6;
    const int n0 = (blockIdx.x % 6) * BN;
    const int m0 = blockIdx.y * BM;
    const int wm = warp & 1, wn = warp >> 1;

    const float* W = (w == 0 ? Wq : w == 1 ? Wk : w == 2 ? Wv : Ws);
    const float* bias = (w == 0 ? b0 : w == 1 ? b1 : w == 2 ? b2 : b3);
    float* out = (w == 0 ? o0 : w == 1 ? o1 : w == 2 ? o2 : o3);

    uint32_t smb = (uint32_t)__cvta_generic_to_shared(sm);

    float c[4][4][4];
#pragma unroll
    for (int mi = 0; mi < 4; mi++)
#pragma unroll
        for (int ni = 0; ni < 4; ni++)
#pragma unroll
            for (int r = 0; r < 4; r++) c[mi][ni][r] = 0.f;

    auto load_stage = [&](int slot, int kt) {
        int k0 = kt * BK;
        uint32_t AsB = smb + (uint32_t)(slot * STAGE_FLOATS) * 4u;
        uint32_t BsB = AsB + AS_FLOATS * 4u;
#pragma unroll
        for (int s = 0; s < 4; s++) {
            int i = t + s * 256;
            int row = i >> 3, c4 = (i & 7) * 4;
            int grow = m0 + row;
            const float* src = A + (size_t)(grow < NN ? grow : 0) * DD + k0 + c4;
            cp16(AsB + (uint32_t)(row * SA + c4) * 4u, src);
        }
#pragma unroll
        for (int s = 0; s < 4; s++) {
            int i = t + s * 256;
            int row = i >> 5, c4 = (i & 31) * 4;
            const float* src = W + (size_t)(k0 + row) * DD + n0 + c4;
            cp16(BsB + (uint32_t)(row * SB + c4) * 4u, src);
        }
    };

#pragma unroll
    for (int s = 0; s < GSTAGES; s++) {
        load_stage(s, s);
        cp_commit();
    }

    for (int kt = 0; kt < NKT; kt++) {
        cp_wait2();
        __syncthreads();
        const float* As = sm + (kt % GSTAGES) * STAGE_FLOATS;
        const float* Bs = As + AS_FLOATS;
#pragma unroll
        for (int ks = 0; ks < 4; ks++) {
            int k0s = ks * 8;
            uint32_t a[4][4], b[4][2];
#pragma unroll
            for (int mi = 0; mi < 4; mi++) {
                int mrow = wm * 64 + mi * 16 + g;
                const float* p = As + mrow * SA + k0s + qd;
                a[mi][0] = f2tf32(p[0]);
                a[mi][1] = f2tf32(p[8 * SA]);
                a[mi][2] = f2tf32(p[4]);
                a[mi][3] = f2tf32(p[8 * SA + 4]);
            }
#pragma unroll
            for (int ni = 0; ni < 4; ni++) {
                int ncol = wn * 32 + ni * 8 + g;
                const float* p = Bs + (k0s + qd) * SB + ncol;
                b[ni][0] = f2tf32(p[0]);
                b[ni][1] = f2tf32(p[4 * SB]);
            }
#pragma unroll
            for (int mi = 0; mi < 4; mi++)
#pragma unroll
                for (int ni = 0; ni < 4; ni++) mma_tf32(c[mi][ni], a[mi], b[ni]);
        }
        __syncthreads();
        if (kt + GSTAGES < NKT) load_stage(kt % GSTAGES, kt + GSTAGES);
        cp_commit();
    }

#pragma unroll
    for (int mi = 0; mi < 4; mi++) {
#pragma unroll
        for (int rh = 0; rh < 2; rh++) {
            int grow = m0 + wm * 64 + mi * 16 + rh * 8 + g;
            if (grow >= NN) continue;
            float* orow = out + (size_t)grow * DD + n0;
#pragma unroll
            for (int ni = 0; ni < 4; ni++) {
                int col = wn * 32 + ni * 8 + 2 * qd;
                float2 val;
                val.x = c[mi][ni][rh * 2 + 0] + bias[n0 + col];
                val.y = c[mi][ni][rh * 2 + 1] + bias[n0 + col + 1];
                *(float2*)(orow + col) = val;
            }
        }
    }
}

// ================= P[n, h*16+i] = sum_c q[n, h*C+c] * WeT[(h*C+c)*16 + i] =================
// WeT layout makes the weight loads coalesced (two 64B chunks per warp per c).
__global__ void __launch_bounds__(256) p_kernel(const float* __restrict__ q,
                                                const float* __restrict__ WeT,
                                                float* __restrict__ P) {
    __shared__ float qs[4][DD];
    int nb = blockIdx.x * 4;
    for (int idx = threadIdx.x; idx < 4 * DD; idx += 256) {
        int nn = nb + idx / DD;
        qs[idx / DD][idx % DD] = (nn < NN) ? q[(size_t)nn * DD + (idx % DD)] : 0.f;
    }
    __syncthreads();
    int local = threadIdx.x >> 6;
    int t64 = threadIdx.x & 63;
    int n = nb + local;
    if (n >= NN) return;
    int h = t64 >> 4, i = t64 & 15;
    const float* qq = qs[local] + h * CC;
    const float* wt = WeT + (size_t)(h * CC) * 16 + i;
    float s = 0.f;
#pragma unroll 4
    for (int c = 0; c < CC; c++) s = fmaf(qq[c], wt[c * 16], s);
    P[(size_t)n * (HH * EDIMF) + t64] = s;
}

// ================= fused attention: warp per node (alpha + softmax + aggregate) =================
__global__ void __launch_bounds__(256) node_fused_kernel(
    const float* __restrict__ q, const float* __restrict__ kk, const float* __restrict__ v,
    const float* __restrict__ skip, const float* __restrict__ efc, const float* __restrict__ P,
    const int* __restrict__ rowptr, const int* __restrict__ srcs,
    const float* __restrict__ We, float* __restrict__ galpha,
    float* __restrict__ out, int gelu) {
    __shared__ float abuf[8][WDEG * HH];
    __shared__ float Ssm[8][2 * 32];
    const int wid = threadIdx.x >> 5, lane = threadIdx.x & 31;
    const int n = blockIdx.x * 8 + wid;
    if (n >= NN) return;
    const int start = rowptr[n], end = rowptr[n + 1];
    const int deg = end - start;
    const unsigned FULL = 0xffffffffu;
    const int h = lane >> 3, lg = lane & 7;

    float* wp = (deg <= WDEG) ? abuf[wid] : (galpha + (size_t)start * HH);

    const float2* qr = (const float2*)(q + (size_t)n * DD + h * CC);
    float2 qv[12];
#pragma unroll
    for (int j = 0; j < 12; j++) qv[j] = qr[lg + 8 * j];
    const float p0 = P[(size_t)n * (HH * EDIMF) + h * EDIMF + lg];
    const float p1 = P[(size_t)n * (HH * EDIMF) + h * EDIMF + lg + 8];

    // ---- pass A: alphas ----
    for (int base = 0; base < deg; base += 32) {
        int cnt = min(32, deg - base);
        int srcReg = (base + lane < deg) ? srcs[start + base + lane] : 0;
        for (int i = 0; i < cnt; i++) {
            int src = __shfl_sync(FULL, srcReg, i);
            int e = start + base + i;
            const float2* kr = (const float2*)(kk + (size_t)src * DD + h * CC);
            float s = 0.f;
#pragma unroll
            for (int j = 0; j < 12; j++) {
                float2 kv = kr[lg + 8 * j];
                s = fmaf(qv[j].x, kv.x, s);
                s = fmaf(qv[j].y, kv.y, s);
            }
            s = fmaf(efc[(size_t)e * EDIMF + lg], p0, s);
            s = fmaf(efc[(size_t)e * EDIMF + lg + 8], p1, s);
            s += __shfl_xor_sync(FULL, s, 1);
            s += __shfl_xor_sync(FULL, s, 2);
            s += __shfl_xor_sync(FULL, s, 4);
            if (lg == 0) wp[(base + i) * HH + h] = s * 0.07216878364870322f;
        }
    }
    __syncwarp();

    // ---- softmax per head ----
    if (lane < HH) {
        float m = -1e30f;
        for (int i = 0; i < deg; i++) m = fmaxf(m, wp[i * HH + lane]);
        float ssum = 0.f;
        for (int i = 0; i < deg; i++) {
            float wv = expf(wp[i * HH + lane] - m);
            wp[i * HH + lane] = wv;
            ssum += wv;
        }
        float inv = 1.f / (ssum + 1e-16f);
        for (int i = 0; i < deg; i++) wp[i * HH + lane] *= inv;
    }
    __syncwarp();

    // ---- pass B: aggregate ----
    float acc[24];
#pragma unroll
    for (int j = 0; j < 24; j++) acc[j] = 0.f;
    float sa = 0.f, sb = 0.f;
    const int iA = lane & 15;
    const int hA = lane >> 4, hB = 2 + (lane >> 4);
    for (int base = 0; base < deg; base += 32) {
        int cnt = min(32, deg - base);
        int srcReg = (base + lane < deg) ? srcs[start + base + lane] : 0;
        for (int i = 0; i < cnt; i++) {
            int src = __shfl_sync(FULL, srcReg, i);
            int idx = base + i;
            const float* vr = v + (size_t)src * DD;
            float w0 = wp[idx * HH + 0];
            float w1 = wp[idx * HH + 1];
            float w2 = wp[idx * HH + 2];
            float w3 = wp[idx * HH + 3];
#pragma unroll
            for (int j = 0; j < 24; j++) {
                float wj = (j < 6) ? w0 : (j < 12) ? w1 : (j < 18) ? w2 : w3;
                acc[j] = fmaf(wj, vr[lane + 32 * j], acc[j]);
            }
            float efA = efc[(size_t)(start + idx) * EDIMF + iA];
            sa = fmaf(wp[idx * HH + hA], efA, sa);
            sb = fmaf(wp[idx * HH + hB], efA, sb);
        }
    }
    Ssm[wid][lane] = sa;
    Ssm[wid][lane + 32] = sb;
    __syncwarp();

    // ---- epilogue ----
    const float* sk = skip + (size_t)n * DD;
    float* orow = out + (size_t)n * DD;
#pragma unroll
    for (int j = 0; j < 24; j++) {
        int c = lane + 32 * j;
        int hh = j / 6;
        float val = acc[j];
#pragma unroll
        for (int i = 0; i < 16; i++)
            val = fmaf(Ssm[wid][hh * 16 + i], We[(size_t)i * DD + c], val);
        val += sk[c];
        if (gelu) val = 0.5f * val * (1.f + erff(val * 0.7071067811865475f));
        orow[c] = val;
    }
}

// ================= layernorm + global mean pool =================
__global__ void ln_pool_kernel(const float* __restrict__ h, float* __restrict__ out) {
    __shared__ float red[256];
    int t = threadIdx.x;
    float acc0 = 0.f, acc1 = 0.f, acc2 = 0.f;
    for (int n = blockIdx.x; n < NN; n += gridDim.x) {
        const float* row = h + (size_t)n * DD;
        float v0 = row[t], v1 = row[t + 256], v2 = row[t + 512];
        red[t] = v0 + v1 + v2;
        __syncthreads();
        for (int off = 128; off > 0; off >>= 1) {
            if (t < off) red[t] += red[t + off];
            __syncthreads();
        }
        float mu = red[0] * (1.f / DD);
        __syncthreads();
        float d0 = v0 - mu, d1 = v1 - mu, d2 = v2 - mu;
        red[t] = d0 * d0 + d1 * d1 + d2 * d2;
        __syncthreads();
        for (int off = 128; off > 0; off >>= 1) {
            if (t < off) red[t] += red[t + off];
            __syncthreads();
        }
        float rstd = rsqrtf(red[0] * (1.f / DD) + 1e-5f);
        __syncthreads();
        acc0 += d0 * rstd;
        acc1 += d1 * rstd;
        acc2 += d2 * rstd;
    }
    atomicAdd(&out[t], acc0);
    atomicAdd(&out[t + 256], acc1);
    atomicAdd(&out[t + 512], acc2);
}

__global__ void ln_final_kernel(float* __restrict__ out, const float* __restrict__ g,
                                const float* __restrict__ b) {
    int c = threadIdx.x + blockIdx.x * blockDim.x;
    if (c < DD) out[c] = out[c] * g[c] * (1.f / NN) + b[c];
}

// ================= launch =================
extern "C" void kernel_launch(void* const* d_in, const int* in_sizes, int n_in,
                              void* d_out, int out_size) {
    const float* x          = (const float*)d_in[0];
    const float* edge_attr  = (const float*)d_in[1];
    const int*   edge_index = (const int*)d_in[2];
    const float* rel_emb    = (const float*)d_in[3];
    const float* W_edge     = (const float*)d_in[4];
    const float* b_edge     = (const float*)d_in[5];
    const float* Wk         = (const float*)d_in[6];
    const float* bk         = (const float*)d_in[7];
    const float* Wq         = (const float*)d_in[8];
    const float* bq         = (const float*)d_in[9];
    const float* Wv         = (const float*)d_in[10];
    const float* bv         = (const float*)d_in[11];
    const float* We         = (const float*)d_in[12];
    const float* Wskip      = (const float*)d_in[13];
    const float* bskip      = (const float*)d_in[14];
    const float* ln_g       = (const float*)d_in[15];
    const float* ln_b       = (const float*)d_in[16];
    float* out = (float*)d_out;

    float *bufA, *bufB, *q, *k, *v, *skip, *ef, *efc, *alpha, *P, *WeT;
    int *rowptr, *cnt, *cur, *srcidx;
    cudaGetSymbolAddress((void**)&bufA, g_bufA);
    cudaGetSymbolAddress((void**)&bufB, g_bufB);
    cudaGetSymbolAddress((void**)&q, g_q);
    cudaGetSymbolAddress((void**)&k, g_k);
    cudaGetSymbolAddress((void**)&v, g_v);
    cudaGetSymbolAddress((void**)&skip, g_skip);
    cudaGetSymbolAddress((void**)&ef, g_ef);
    cudaGetSymbolAddress((void**)&efc, g_efcsr);
    cudaGetSymbolAddress((void**)&alpha, g_alpha);
    cudaGetSymbolAddress((void**)&P, g_P);
    cudaGetSymbolAddress((void**)&WeT, g_WeT);
    cudaGetSymbolAddress((void**)&rowptr, g_rowptr);
    cudaGetSymbolAddress((void**)&cnt, g_cnt);
    cudaGetSymbolAddress((void**)&cur, g_cur);
    cudaGetSymbolAddress((void**)&srcidx, g_srcidx);

    cudaFuncSetAttribute(gemm4_kernel, cudaFuncAttributeMaxDynamicSharedMemorySize, GEMM_SMEM);

    cudaMemsetAsync(cnt, 0, NN * sizeof(int));
    cudaMemsetAsync(cur, 0, NN * sizeof(int));
    // launch order chosen so p_kernel(L0) is the 4th kernel = ncu capture slot
    prep1_kernel<<<(EE + 255) / 256, 256>>>(edge_index, cnt, We, WeT);   // #1
    scan_kernel<<<1, 1024>>>(cnt, rowptr);                               // #2

    const float* hin = x;
    for (int l = 0; l < LL; l++) {
        const float* We_l = We + (size_t)l * EDIMF * DD;
        gemm4_kernel<<<dim3(24, (NN + BM - 1) / BM), 256, GEMM_SMEM>>>(  // #3 (l=0)
            hin,
            Wq + (size_t)l * DD * DD, Wk + (size_t)l * DD * DD,
            Wv + (size_t)l * DD * DD, Wskip + (size_t)l * DD * DD,
            bq + (size_t)l * DD, bk + (size_t)l * DD, bv + (size_t)l * DD, bskip + (size_t)l * DD,
            q, k, v, skip);
        p_kernel<<<(NN + 3) / 4, 256>>>(q, WeT + (size_t)l * DD * EDIMF, P);  // #4 (l=0) <- profiled
        if (l == 0) {
            ef_kernel<<<(EE + 255) / 256, 256>>>(edge_attr, rel_emb, W_edge, b_edge, ef);  // #5
            scatter_kernel<<<(EE + 255) / 256, 256>>>(edge_index, rowptr, cur, srcidx, ef, efc);  // #6
        }
        float* hout = (l & 1) ? bufB : bufA;
        node_fused_kernel<<<(NN + 7) / 8, 256>>>(q, k, v, skip, efc, P, rowptr, srcidx, We_l,
                                                 alpha, hout, (l < LL - 1) ? 1 : 0);
        hin = hout;
    }

    cudaMemsetAsync(out, 0, DD * sizeof(float));
    ln_pool_kernel<<<1024, 256>>>(hin, out);
    ln_final_kernel<<<3, 256>>>(out, ln_g, ln_b);
}

// round 9
// speedup vs baseline: 2.4312x; 1.0576x over previous
#include <cuda_runtime.h>
#include <cstdint>

#define NN 10000
#define EE 100000
#define DD 768
#define HH 4
#define CC 192
#define LL 3
#define EDIMF 16
#define NRELC 10

// GEMM tiling: block 128x128, 8 warps as 2(m) x 4(n), warp tile 64x32
#define BM 128
#define BN 128
#define BK 32
#define NKT (DD / BK)
#define GSTAGES 3
#define SA 36
#define SB 136
#define AS_FLOATS (BM * SA)
#define BS_FLOATS (BK * SB)
#define STAGE_FLOATS (AS_FLOATS + BS_FLOATS)
#define GEMM_SMEM (GSTAGES * STAGE_FLOATS * 4)   // ~105 KB -> 2 CTA/SM

#define WDEG 64

// ---------------- scratch (static device globals; no allocation) ----------------
__device__ float g_bufA[NN * DD];
__device__ float g_bufB[NN * DD];     // holds tf32-rounded x for layer 0, then hout(1)
__device__ float g_q[NN * DD];
__device__ float g_k[NN * DD];
__device__ float g_v[NN * DD];
__device__ float g_skip[NN * DD];
__device__ float g_Wt[LL * 4 * DD * DD];   // tf32-rounded weights [l][w][k][n]
__device__ float g_ef[EE * EDIMF];
__device__ float g_efcsr[EE * EDIMF];
__device__ float g_alpha[EE * HH];
__device__ float g_P[NN * HH * EDIMF];
__device__ float g_WeT[LL * DD * EDIMF];
__device__ int   g_rowptr[NN + 1];
__device__ int   g_cnt[NN];
__device__ int   g_cur[NN];
__device__ int   g_srcidx[EE];

// ---------------- helpers ----------------
__device__ __forceinline__ void cp16(uint32_t dst, const float* src) {
    asm volatile("cp.async.cg.shared.global [%0], [%1], 16;" ::"r"(dst),
                 "l"(__cvta_generic_to_global(src)));
}
__device__ __forceinline__ void cp_commit() { asm volatile("cp.async.commit_group;"); }
__device__ __forceinline__ void cp_wait2() { asm volatile("cp.async.wait_group 2;"); }

__device__ __forceinline__ uint32_t f2tf32(float f) {
    uint32_t u;
    asm("cvt.rna.tf32.f32 %0, %1;" : "=r"(u) : "f"(f));
    return u;
}
__device__ __forceinline__ float round_tf32(float f) { return __uint_as_float(f2tf32(f)); }

__device__ __forceinline__ void mma_tf32(float* c, const uint32_t* a, const uint32_t* b) {
    asm volatile(
        "mma.sync.aligned.m16n8k8.row.col.f32.tf32.tf32.f32 "
        "{%0,%1,%2,%3}, {%4,%5,%6,%7}, {%8,%9}, {%0,%1,%2,%3};"
        : "+f"(c[0]), "+f"(c[1]), "+f"(c[2]), "+f"(c[3])
        : "r"(a[0]), "r"(a[1]), "r"(a[2]), "r"(a[3]), "r"(b[0]), "r"(b[1]));
}

// ================= prep0: tf32-round all GEMM weights + x (float4-vectorized) =================
#define WELEMS (LL * 4 * DD * DD / 4)   // 1,769,472 float4
#define XELEMS (NN * DD / 4)            // 1,920,000 float4
__global__ void round_kernel(const float* __restrict__ Wq, const float* __restrict__ Wk,
                             const float* __restrict__ Wv, const float* __restrict__ Ws,
                             const float* __restrict__ x,
                             float* __restrict__ Wt, float* __restrict__ xr) {
    int idx = blockIdx.x * blockDim.x + threadIdx.x;
    if (idx < WELEMS) {
        int z = idx / (DD * DD / 4);       // l*4+w
        int rem = idx % (DD * DD / 4);
        int l = z >> 2, w = z & 3;
        const float* W = (w == 0 ? Wq : w == 1 ? Wk : w == 2 ? Wv : Ws) + (size_t)l * DD * DD;
        float4 val = ((const float4*)W)[rem];
        val.x = round_tf32(val.x); val.y = round_tf32(val.y);
        val.z = round_tf32(val.z); val.w = round_tf32(val.w);
        ((float4*)Wt)[idx] = val;
    } else if (idx < WELEMS + XELEMS) {
        int i = idx - WELEMS;
        float4 val = ((const float4*)x)[i];
        val.x = round_tf32(val.x); val.y = round_tf32(val.y);
        val.z = round_tf32(val.z); val.w = round_tf32(val.w);
        ((float4*)xr)[i] = val;
    }
}

// ================= prep1: edge count for CSR + build WeT for all layers =================
__global__ void prep1_kernel(const int* __restrict__ edge_index, int* __restrict__ cnt,
                             const float* __restrict__ We, float* __restrict__ WeT) {
    int idx = blockIdx.x * blockDim.x + threadIdx.x;
    if (idx < EE) atomicAdd(&cnt[edge_index[EE + idx]], 1);
    if (idx < LL * DD * EDIMF) {
        int l = idx / (DD * EDIMF);
        int rem = idx % (DD * EDIMF);
        int d = rem >> 4, i = rem & 15;
        WeT[idx] = We[(size_t)l * EDIMF * DD + (size_t)i * DD + d];
    }
}

// ================= edge feature projection =================
__global__ void ef_kernel(const float* __restrict__ edge_attr, const float* __restrict__ rel_emb,
                          const float* __restrict__ W_edge, const float* __restrict__ b_edge,
                          float* __restrict__ ef) {
    __shared__ float sW[EDIMF * EDIMF];
    __shared__ float sB[EDIMF];
    __shared__ float sR[NRELC * (EDIMF - 1)];
    int t = threadIdx.x;
    if (t < EDIMF * EDIMF) sW[t] = W_edge[t];
    if (t < EDIMF) sB[t] = b_edge[t];
    if (t < NRELC * (EDIMF - 1)) sR[t] = rel_emb[t];
    __syncthreads();
    int e = blockIdx.x * blockDim.x + t;
    if (e >= EE) return;
    int r = (int)edge_attr[2 * e];
    r = min(max(r, 0), NRELC - 1);
    float feat[EDIMF];
#pragma unroll
    for (int i = 0; i < EDIMF - 1; i++) feat[i] = sR[r * (EDIMF - 1) + i];
    feat[EDIMF - 1] = edge_attr[2 * e + 1];
#pragma unroll
    for (int j = 0; j < EDIMF; j++) {
        float s = sB[j];
#pragma unroll
        for (int i = 0; i < EDIMF; i++) s += feat[i] * sW[i * EDIMF + j];
        ef[(size_t)e * EDIMF + j] = s;
    }
}

// ================= CSR scan =================
__global__ void scan_kernel(const int* __restrict__ cnt, int* __restrict__ rowptr) {
    __shared__ int s[1024];
    int t = threadIdx.x;
    int carry = 0;
    if (t == 0) rowptr[0] = 0;
    for (int base = 0; base < NN; base += 1024) {
        int i = base + t;
        s[t] = (i < NN) ? cnt[i] : 0;
        __syncthreads();
        for (int off = 1; off < 1024; off <<= 1) {
            int add = (t >= off) ? s[t - off] : 0;
            __syncthreads();
            s[t] += add;
            __syncthreads();
        }
        if (i < NN) rowptr[i + 1] = carry + s[t];
        int tot = s[1023];
        __syncthreads();
        carry += tot;
    }
}

__global__ void scatter_kernel(const int* __restrict__ edge_index, const int* __restrict__ rowptr,
                               int* __restrict__ cur, int* __restrict__ srcs,
                               const float* __restrict__ ef, float* __restrict__ efc) {
    int e = blockIdx.x * blockDim.x + threadIdx.x;
    if (e >= EE) return;
    int dst = edge_index[EE + e];
    int pos = rowptr[dst] + atomicAdd(&cur[dst], 1);
    srcs[pos] = edge_index[e];
    const float4* s = (const float4*)(ef + (size_t)e * EDIMF);
    float4* d = (float4*)(efc + (size_t)pos * EDIMF);
    d[0] = s[0]; d[1] = s[1]; d[2] = s[2]; d[3] = s[3];
}

// ================= fused QKVS GEMM via mma.sync tf32 (pre-rounded inputs, no cvt) =================
__global__ void __launch_bounds__(256, 2) gemm4_kernel(
    const float* __restrict__ A, const float* __restrict__ Wt,
    const float* __restrict__ b0, const float* __restrict__ b1,
    const float* __restrict__ b2, const float* __restrict__ b3,
    float* __restrict__ o0, float* __restrict__ o1,
    float* __restrict__ o2, float* __restrict__ o3) {
    extern __shared__ float sm[];
    const int t = threadIdx.x;
    const int warp = t >> 5, lane = t & 31;
    const int g = lane >> 2, qd = lane & 3;
    const int w = blockIdx.x / 6;
    const int n0 = (blockIdx.x % 6) * BN;
    const int m0 = blockIdx.y * BM;
    const int wm = warp & 1, wn = warp >> 1;

    const float* W = Wt + (size_t)w * DD * DD;
    const float* bias = (w == 0 ? b0 : w == 1 ? b1 : w == 2 ? b2 : b3);
    float* out = (w == 0 ? o0 : w == 1 ? o1 : w == 2 ? o2 : o3);

    uint32_t smb = (uint32_t)__cvta_generic_to_shared(sm);

    float c[4][4][4];
#pragma unroll
    for (int mi = 0; mi < 4; mi++)
#pragma unroll
        for (int ni = 0; ni < 4; ni++)
#pragma unroll
            for (int r = 0; r < 4; r++) c[mi][ni][r] = 0.f;

    auto load_stage = [&](int slot, int kt) {
        int k0 = kt * BK;
        uint32_t AsB = smb + (uint32_t)(slot * STAGE_FLOATS) * 4u;
        uint32_t BsB = AsB + AS_FLOATS * 4u;
#pragma unroll
        for (int s = 0; s < 4; s++) {
            int i = t + s * 256;
            int row = i >> 3, c4 = (i & 7) * 4;
            int grow = m0 + row;
            const float* src = A + (size_t)(grow < NN ? grow : 0) * DD + k0 + c4;
            cp16(AsB + (uint32_t)(row * SA + c4) * 4u, src);
        }
#pragma unroll
        for (int s = 0; s < 4; s++) {
            int i = t + s * 256;
            int row = i >> 5, c4 = (i & 31) * 4;
            const float* src = W + (size_t)(k0 + row) * DD + n0 + c4;
            cp16(BsB + (uint32_t)(row * SB + c4) * 4u, src);
        }
    };

#pragma unroll
    for (int s = 0; s < GSTAGES; s++) {
        load_stage(s, s);
        cp_commit();
    }

    for (int kt = 0; kt < NKT; kt++) {
        cp_wait2();
        __syncthreads();
        const uint32_t* As = (const uint32_t*)(sm + (kt % GSTAGES) * STAGE_FLOATS);
        const uint32_t* Bs = As + AS_FLOATS;
#pragma unroll
        for (int ks = 0; ks < 4; ks++) {
            int k0s = ks * 8;
            uint32_t a[4][4], b[4][2];
#pragma unroll
            for (int mi = 0; mi < 4; mi++) {
                int mrow = wm * 64 + mi * 16 + g;
                const uint32_t* p = As + mrow * SA + k0s + qd;
                a[mi][0] = p[0];
                a[mi][1] = p[8 * SA];
                a[mi][2] = p[4];
                a[mi][3] = p[8 * SA + 4];
            }
#pragma unroll
            for (int ni = 0; ni < 4; ni++) {
                int ncol = wn * 32 + ni * 8 + g;
                const uint32_t* p = Bs + (k0s + qd) * SB + ncol;
                b[ni][0] = p[0];
                b[ni][1] = p[4 * SB];
            }
#pragma unroll
            for (int mi = 0; mi < 4; mi++)
#pragma unroll
                for (int ni = 0; ni < 4; ni++) mma_tf32(c[mi][ni], a[mi], b[ni]);
        }
        __syncthreads();
        if (kt + GSTAGES < NKT) load_stage(kt % GSTAGES, kt + GSTAGES);
        cp_commit();
    }

#pragma unroll
    for (int mi = 0; mi < 4; mi++) {
#pragma unroll
        for (int rh = 0; rh < 2; rh++) {
            int grow = m0 + wm * 64 + mi * 16 + rh * 8 + g;
            if (grow >= NN) continue;
            float* orow = out + (size_t)grow * DD + n0;
#pragma unroll
            for (int ni = 0; ni < 4; ni++) {
                int col = wn * 32 + ni * 8 + 2 * qd;
                float2 val;
                val.x = c[mi][ni][rh * 2 + 0] + bias[n0 + col];
                val.y = c[mi][ni][rh * 2 + 1] + bias[n0 + col + 1];
                *(float2*)(orow + col) = val;
            }
        }
    }
}

// ================= P[n, h*16+i] = sum_c q[n, h*C+c] * WeT[(h*C+c)*16 + i] =================
__global__ void __launch_bounds__(256) p_kernel(const float* __restrict__ q,
                                                const float* __restrict__ WeT,
                                                float* __restrict__ P) {
    __shared__ float qs[4][DD];
    int nb = blockIdx.x * 4;
    for (int idx = threadIdx.x; idx < 4 * DD; idx += 256) {
        int nn = nb + idx / DD;
        qs[idx / DD][idx % DD] = (nn < NN) ? q[(size_t)nn * DD + (idx % DD)] : 0.f;
    }
    __syncthreads();
    int local = threadIdx.x >> 6;
    int t64 = threadIdx.x & 63;
    int n = nb + local;
    if (n >= NN) return;
    int h = t64 >> 4, i = t64 & 15;
    const float* qq = qs[local] + h * CC;
    const float* wt = WeT + (size_t)(h * CC) * 16 + i;
    float s0 = 0.f, s1 = 0.f, s2 = 0.f, s3 = 0.f;
#pragma unroll 4
    for (int c = 0; c < CC; c += 4) {
        s0 = fmaf(qq[c + 0], wt[(c + 0) * 16], s0);
        s1 = fmaf(qq[c + 1], wt[(c + 1) * 16], s1);
        s2 = fmaf(qq[c + 2], wt[(c + 2) * 16], s2);
        s3 = fmaf(qq[c + 3], wt[(c + 3) * 16], s3);
    }
    P[(size_t)n * (HH * EDIMF) + t64] = (s0 + s1) + (s2 + s3);
}

// ================= fused attention: warp per node =================
__global__ void __launch_bounds__(256) node_fused_kernel(
    const float* __restrict__ q, const float* __restrict__ kk, const float* __restrict__ v,
    const float* __restrict__ skip, const float* __restrict__ efc, const float* __restrict__ P,
    const int* __restrict__ rowptr, const int* __restrict__ srcs,
    const float* __restrict__ We, float* __restrict__ galpha,
    float* __restrict__ out, int gelu) {
    __shared__ float abuf[8][WDEG * HH];
    __shared__ float Ssm[8][2 * 32];
    const int wid = threadIdx.x >> 5, lane = threadIdx.x & 31;
    const int n = blockIdx.x * 8 + wid;
    if (n >= NN) return;
    const int start = rowptr[n], end = rowptr[n + 1];
    const int deg = end - start;
    const unsigned FULL = 0xffffffffu;
    const int h = lane >> 3, lg = lane & 7;

    float* wp = (deg <= WDEG) ? abuf[wid] : (galpha + (size_t)start * HH);

    const float2* qr = (const float2*)(q + (size_t)n * DD + h * CC);
    float2 qv[12];
#pragma unroll
    for (int j = 0; j < 12; j++) qv[j] = qr[lg + 8 * j];
    const float p0 = P[(size_t)n * (HH * EDIMF) + h * EDIMF + lg];
    const float p1 = P[(size_t)n * (HH * EDIMF) + h * EDIMF + lg + 8];

    for (int base = 0; base < deg; base += 32) {
        int cnt = min(32, deg - base);
        int srcReg = (base + lane < deg) ? srcs[start + base + lane] : 0;
        for (int i = 0; i < cnt; i++) {
            int src = __shfl_sync(FULL, srcReg, i);
            int e = start + base + i;
            const float2* kr = (const float2*)(kk + (size_t)src * DD + h * CC);
            float s = 0.f;
#pragma unroll
            for (int j = 0; j < 12; j++) {
                float2 kv = kr[lg + 8 * j];
                s = fmaf(qv[j].x, kv.x, s);
                s = fmaf(qv[j].y, kv.y, s);
            }
            s = fmaf(efc[(size_t)e * EDIMF + lg], p0, s);
            s = fmaf(efc[(size_t)e * EDIMF + lg + 8], p1, s);
            s += __shfl_xor_sync(FULL, s, 1);
            s += __shfl_xor_sync(FULL, s, 2);
            s += __shfl_xor_sync(FULL, s, 4);
            if (lg == 0) wp[(base + i) * HH + h] = s * 0.07216878364870322f;
        }
    }
    __syncwarp();

    if (lane < HH) {
        float m = -1e30f;
        for (int i = 0; i < deg; i++) m = fmaxf(m, wp[i * HH + lane]);
        float ssum = 0.f;
        for (int i = 0; i < deg; i++) {
            float wv = expf(wp[i * HH + lane] - m);
            wp[i * HH + lane] = wv;
            ssum += wv;
        }
        float inv = 1.f / (ssum + 1e-16f);
        for (int i = 0; i < deg; i++) wp[i * HH + lane] *= inv;
    }
    __syncwarp();

    float acc[24];
#pragma unroll
    for (int j = 0; j < 24; j++) acc[j] = 0.f;
    float sa = 0.f, sb = 0.f;
    const int iA = lane & 15;
    const int hA = lane >> 4, hB = 2 + (lane >> 4);
    for (int base = 0; base < deg; base += 32) {
        int cnt = min(32, deg - base);
        int srcReg = (base + lane < deg) ? srcs[start + base + lane] : 0;
        for (int i = 0; i < cnt; i++) {
            int src = __shfl_sync(FULL, srcReg, i);
            int idx = base + i;
            const float* vr = v + (size_t)src * DD;
            float w0 = wp[idx * HH + 0];
            float w1 = wp[idx * HH + 1];
            float w2 = wp[idx * HH + 2];
            float w3 = wp[idx * HH + 3];
#pragma unroll
            for (int j = 0; j < 24; j++) {
                float wj = (j < 6) ? w0 : (j < 12) ? w1 : (j < 18) ? w2 : w3;
                acc[j] = fmaf(wj, vr[lane + 32 * j], acc[j]);
            }
            float efA = efc[(size_t)(start + idx) * EDIMF + iA];
            sa = fmaf(wp[idx * HH + hA], efA, sa);
            sb = fmaf(wp[idx * HH + hB], efA, sb);
        }
    }
    Ssm[wid][lane] = sa;
    Ssm[wid][lane + 32] = sb;
    __syncwarp();

    const float* sk = skip + (size_t)n * DD;
    float* orow = out + (size_t)n * DD;
#pragma unroll
    for (int j = 0; j < 24; j++) {
        int c = lane + 32 * j;
        int hh = j / 6;
        float val = acc[j];
#pragma unroll
        for (int i = 0; i < 16; i++)
            val = fmaf(Ssm[wid][hh * 16 + i], We[(size_t)i * DD + c], val);
        val += sk[c];
        if (gelu) {
            val = 0.5f * val * (1.f + erff(val * 0.7071067811865475f));
            val = round_tf32(val);   // h feeds only next layer's GEMMs -> pre-round here
        }
        orow[c] = val;
    }
}

// ================= layernorm + global mean pool =================
__global__ void ln_pool_kernel(const float* __restrict__ h, float* __restrict__ out) {
    __shared__ float red[256];
    int t = threadIdx.x;
    float acc0 = 0.f, acc1 = 0.f, acc2 = 0.f;
    for (int n = blockIdx.x; n < NN; n += gridDim.x) {
        const float* row = h + (size_t)n * DD;
        float v0 = row[t], v1 = row[t + 256], v2 = row[t + 512];
        red[t] = v0 + v1 + v2;
        __syncthreads();
        for (int off = 128; off > 0; off >>= 1) {
            if (t < off) red[t] += red[t + off];
            __syncthreads();
        }
        float mu = red[0] * (1.f / DD);
        __syncthreads();
        float d0 = v0 - mu, d1 = v1 - mu, d2 = v2 - mu;
        red[t] = d0 * d0 + d1 * d1 + d2 * d2;
        __syncthreads();
        for (int off = 128; off > 0; off >>= 1) {
            if (t < off) red[t] += red[t + off];
            __syncthreads();
        }
        float rstd = rsqrtf(red[0] * (1.f / DD) + 1e-5f);
        __syncthreads();
        acc0 += d0 * rstd;
        acc1 += d1 * rstd;
        acc2 += d2 * rstd;
    }
    atomicAdd(&out[t], acc0);
    atomicAdd(&out[t + 256], acc1);
    atomicAdd(&out[t + 512], acc2);
}

__global__ void ln_final_kernel(float* __restrict__ out, const float* __restrict__ g,
                                const float* __restrict__ b) {
    int c = threadIdx.x + blockIdx.x * blockDim.x;
    if (c < DD) out[c] = out[c] * g[c] * (1.f / NN) + b[c];
}

// ================= launch =================
extern "C" void kernel_launch(void* const* d_in, const int* in_sizes, int n_in,
                              void* d_out, int out_size) {
    const float* x          = (const float*)d_in[0];
    const float* edge_attr  = (const float*)d_in[1];
    const int*   edge_index = (const int*)d_in[2];
    const float* rel_emb    = (const float*)d_in[3];
    const float* W_edge     = (const float*)d_in[4];
    const float* b_edge     = (const float*)d_in[5];
    const float* Wk         = (const float*)d_in[6];
    const float* bk         = (const float*)d_in[7];
    const float* Wq         = (const float*)d_in[8];
    const float* bq         = (const float*)d_in[9];
    const float* Wv         = (const float*)d_in[10];
    const float* bv         = (const float*)d_in[11];
    const float* We         = (const float*)d_in[12];
    const float* Wskip      = (const float*)d_in[13];
    const float* bskip      = (const float*)d_in[14];
    const float* ln_g       = (const float*)d_in[15];
    const float* ln_b       = (const float*)d_in[16];
    float* out = (float*)d_out;

    float *bufA, *bufB, *q, *k, *v, *skip, *ef, *efc, *alpha, *P, *WeT, *Wt;
    int *rowptr, *cnt, *cur, *srcidx;
    cudaGetSymbolAddress((void**)&bufA, g_bufA);
    cudaGetSymbolAddress((void**)&bufB, g_bufB);
    cudaGetSymbolAddress((void**)&q, g_q);
    cudaGetSymbolAddress((void**)&k, g_k);
    cudaGetSymbolAddress((void**)&v, g_v);
    cudaGetSymbolAddress((void**)&skip, g_skip);
    cudaGetSymbolAddress((void**)&ef, g_ef);
    cudaGetSymbolAddress((void**)&efc, g_efcsr);
    cudaGetSymbolAddress((void**)&alpha, g_alpha);
    cudaGetSymbolAddress((void**)&P, g_P);
    cudaGetSymbolAddress((void**)&WeT, g_WeT);
    cudaGetSymbolAddress((void**)&Wt, g_Wt);
    cudaGetSymbolAddress((void**)&rowptr, g_rowptr);
    cudaGetSymbolAddress((void**)&cnt, g_cnt);
    cudaGetSymbolAddress((void**)&cur, g_cur);
    cudaGetSymbolAddress((void**)&srcidx, g_srcidx);

    cudaFuncSetAttribute(gemm4_kernel, cudaFuncAttributeMaxDynamicSharedMemorySize, GEMM_SMEM);

    cudaMemsetAsync(cnt, 0, NN * sizeof(int));
    cudaMemsetAsync(cur, 0, NN * sizeof(int));
    // #1..#3 prep; gemm4(L0) = kernel #4 = ncu capture slot
    round_kernel<<<(WELEMS + XELEMS + 255) / 256, 256>>>(Wq, Wk, Wv, Wskip, x, Wt, bufB);  // #1
    prep1_kernel<<<(EE + 255) / 256, 256>>>(edge_index, cnt, We, WeT);                     // #2
    scan_kernel<<<1, 1024>>>(cnt, rowptr);                                                 // #3

    const float* hin = bufB;   // tf32-rounded x
    for (int l = 0; l < LL; l++) {
        const float* We_l = We + (size_t)l * EDIMF * DD;
        gemm4_kernel<<<dim3(24, (NN + BM - 1) / BM), 256, GEMM_SMEM>>>(                    // #4 (l=0)
            hin, Wt + (size_t)l * 4 * DD * DD,
            bq + (size_t)l * DD, bk + (size_t)l * DD, bv + (size_t)l * DD, bskip + (size_t)l * DD,
            q, k, v, skip);
        p_kernel<<<(NN + 3) / 4, 256>>>(q, WeT + (size_t)l * DD * EDIMF, P);
        if (l == 0) {
            ef_kernel<<<(EE + 255) / 256, 256>>>(edge_attr, rel_emb, W_edge, b_edge, ef);
            scatter_kernel<<<(EE + 255) / 256, 256>>>(edge_index, rowptr, cur, srcidx, ef, efc);
        }
        float* hout = (l & 1) ? bufB : bufA;
        node_fused_kernel<<<(NN + 7) / 8, 256>>>(q, k, v, skip, efc, P, rowptr, srcidx, We_l,
                                                 alpha, hout, (l < LL - 1) ? 1 : 0);
        hin = hout;
    }

    cudaMemsetAsync(out, 0, DD * sizeof(float));
    ln_pool_kernel<<<1024, 256>>>(hin, out);
    ln_final_kernel<<<3, 256>>>(out, ln_g, ln_b);
}

// round 10
// speedup vs baseline: 2.4541x; 1.0094x over previous
#include <cuda_runtime.h>
#include <cstdint>

#define NN 10000
#define EE 100000
#define DD 768
#define HH 4
#define CC 192
#define LL 3
#define EDIMF 16
#define NRELC 10

// GEMM tiling: block 128x128, 8 warps as 2(m) x 4(n), warp tile 64x32
#define BM 128
#define BN 128
#define BK 32
#define NKT (DD / BK)
#define GSTAGES 3
#define SA 36
#define SB 136
#define AS_FLOATS (BM * SA)
#define BS_FLOATS (BK * SB)
#define STAGE_FLOATS (AS_FLOATS + BS_FLOATS)
#define GEMM_SMEM (GSTAGES * STAGE_FLOATS * 4)   // ~105 KB -> 2 CTA/SM

#define WDEG 64
#define HPAD (CC * EDIMF + EDIMF)   // padded per-head WeT stride in smem (3088 floats)

// ---------------- scratch (static device globals; no allocation) ----------------
__device__ float g_bufA[NN * DD];
__device__ float g_bufB[NN * DD];     // tf32-rounded x for layer 0, then hout(1)
__device__ float g_q[NN * DD];
__device__ float g_k[NN * DD];
__device__ float g_v[NN * DD];
__device__ float g_skip[NN * DD];
__device__ float g_Wt[LL * 4 * DD * DD];   // tf32-rounded weights [l][w][k][n]
__device__ float g_ef[EE * EDIMF];
__device__ float g_efcsr[EE * EDIMF];
__device__ float g_alpha[EE * HH];
__device__ float g_P[NN * HH * EDIMF];
__device__ float g_WeT[LL * DD * EDIMF];
__device__ int   g_rowptr[NN + 1];
__device__ int   g_cnt[NN];
__device__ int   g_cur[NN];
__device__ int   g_srcidx[EE];

// ---------------- helpers ----------------
__device__ __forceinline__ void cp16(uint32_t dst, const float* src) {
    asm volatile("cp.async.cg.shared.global [%0], [%1], 16;" ::"r"(dst),
                 "l"(__cvta_generic_to_global(src)));
}
__device__ __forceinline__ void cp_commit() { asm volatile("cp.async.commit_group;"); }
__device__ __forceinline__ void cp_wait1() { asm volatile("cp.async.wait_group 1;"); }

__device__ __forceinline__ uint32_t f2tf32(float f) {
    uint32_t u;
    asm("cvt.rna.tf32.f32 %0, %1;" : "=r"(u) : "f"(f));
    return u;
}
__device__ __forceinline__ float round_tf32(float f) { return __uint_as_float(f2tf32(f)); }

__device__ __forceinline__ void mma_tf32(float* c, const uint32_t* a, const uint32_t* b) {
    asm volatile(
        "mma.sync.aligned.m16n8k8.row.col.f32.tf32.tf32.f32 "
        "{%0,%1,%2,%3}, {%4,%5,%6,%7}, {%8,%9}, {%0,%1,%2,%3};"
        : "+f"(c[0]), "+f"(c[1]), "+f"(c[2]), "+f"(c[3])
        : "r"(a[0]), "r"(a[1]), "r"(a[2]), "r"(a[3]), "r"(b[0]), "r"(b[1]));
}

// ================= prep0: tf32-round all GEMM weights + x =================
#define WELEMS (LL * 4 * DD * DD / 4)
#define XELEMS (NN * DD / 4)
__global__ void round_kernel(const float* __restrict__ Wq, const float* __restrict__ Wk,
                             const float* __restrict__ Wv, const float* __restrict__ Ws,
                             const float* __restrict__ x,
                             float* __restrict__ Wt, float* __restrict__ xr) {
    int idx = blockIdx.x * blockDim.x + threadIdx.x;
    if (idx < WELEMS) {
        int z = idx / (DD * DD / 4);
        int rem = idx % (DD * DD / 4);
        int l = z >> 2, w = z & 3;
        const float* W = (w == 0 ? Wq : w == 1 ? Wk : w == 2 ? Wv : Ws) + (size_t)l * DD * DD;
        float4 val = ((const float4*)W)[rem];
        val.x = round_tf32(val.x); val.y = round_tf32(val.y);
        val.z = round_tf32(val.z); val.w = round_tf32(val.w);
        ((float4*)Wt)[idx] = val;
    } else if (idx < WELEMS + XELEMS) {
        int i = idx - WELEMS;
        float4 val = ((const float4*)x)[i];
        val.x = round_tf32(val.x); val.y = round_tf32(val.y);
        val.z = round_tf32(val.z); val.w = round_tf32(val.w);
        ((float4*)xr)[i] = val;
    }
}

// ================= prep1: edge count for CSR + build WeT =================
__global__ void prep1_kernel(const int* __restrict__ edge_index, int* __restrict__ cnt,
                             const float* __restrict__ We, float* __restrict__ WeT) {
    int idx = blockIdx.x * blockDim.x + threadIdx.x;
    if (idx < EE) atomicAdd(&cnt[edge_index[EE + idx]], 1);
    if (idx < LL * DD * EDIMF) {
        int l = idx / (DD * EDIMF);
        int rem = idx % (DD * EDIMF);
        int d = rem >> 4, i = rem & 15;
        WeT[idx] = We[(size_t)l * EDIMF * DD + (size_t)i * DD + d];
    }
}

// ================= edge feature projection =================
__global__ void ef_kernel(const float* __restrict__ edge_attr, const float* __restrict__ rel_emb,
                          const float* __restrict__ W_edge, const float* __restrict__ b_edge,
                          float* __restrict__ ef) {
    __shared__ float sW[EDIMF * EDIMF];
    __shared__ float sB[EDIMF];
    __shared__ float sR[NRELC * (EDIMF - 1)];
    int t = threadIdx.x;
    if (t < EDIMF * EDIMF) sW[t] = W_edge[t];
    if (t < EDIMF) sB[t] = b_edge[t];
    if (t < NRELC * (EDIMF - 1)) sR[t] = rel_emb[t];
    __syncthreads();
    int e = blockIdx.x * blockDim.x + t;
    if (e >= EE) return;
    int r = (int)edge_attr[2 * e];
    r = min(max(r, 0), NRELC - 1);
    float feat[EDIMF];
#pragma unroll
    for (int i = 0; i < EDIMF - 1; i++) feat[i] = sR[r * (EDIMF - 1) + i];
    feat[EDIMF - 1] = edge_attr[2 * e + 1];
#pragma unroll
    for (int j = 0; j < EDIMF; j++) {
        float s = sB[j];
#pragma unroll
        for (int i = 0; i < EDIMF; i++) s += feat[i] * sW[i * EDIMF + j];
        ef[(size_t)e * EDIMF + j] = s;
    }
}

// ================= CSR scan =================
__global__ void scan_kernel(const int* __restrict__ cnt, int* __restrict__ rowptr) {
    __shared__ int s[1024];
    int t = threadIdx.x;
    int carry = 0;
    if (t == 0) rowptr[0] = 0;
    for (int base = 0; base < NN; base += 1024) {
        int i = base + t;
        s[t] = (i < NN) ? cnt[i] : 0;
        __syncthreads();
        for (int off = 1; off < 1024; off <<= 1) {
            int add = (t >= off) ? s[t - off] : 0;
            __syncthreads();
            s[t] += add;
            __syncthreads();
        }
        if (i < NN) rowptr[i + 1] = carry + s[t];
        int tot = s[1023];
        __syncthreads();
        carry += tot;
    }
}

__global__ void scatter_kernel(const int* __restrict__ edge_index, const int* __restrict__ rowptr,
                               int* __restrict__ cur, int* __restrict__ srcs,
                               const float* __restrict__ ef, float* __restrict__ efc) {
    int e = blockIdx.x * blockDim.x + threadIdx.x;
    if (e >= EE) return;
    int dst = edge_index[EE + e];
    int pos = rowptr[dst] + atomicAdd(&cur[dst], 1);
    srcs[pos] = edge_index[e];
    const float4* s = (const float4*)(ef + (size_t)e * EDIMF);
    float4* d = (float4*)(efc + (size_t)pos * EDIMF);
    d[0] = s[0]; d[1] = s[1]; d[2] = s[2]; d[3] = s[3];
}

// ================= fused QKVS GEMM via mma.sync tf32 (single-sync pipeline) =================
__global__ void __launch_bounds__(256, 2) gemm4_kernel(
    const float* __restrict__ A, const float* __restrict__ Wt,
    const float* __restrict__ b0, const float* __restrict__ b1,
    const float* __restrict__ b2, const float* __restrict__ b3,
    float* __restrict__ o0, float* __restrict__ o1,
    float* __restrict__ o2, float* __restrict__ o3) {
    extern __shared__ float sm[];
    const int t = threadIdx.x;
    const int warp = t >> 5, lane = t & 31;
    const int g = lane >> 2, qd = lane & 3;
    const int w = blockIdx.x / 6;
    const int n0 = (blockIdx.x % 6) * BN;
    const int m0 = blockIdx.y * BM;
    const int wm = warp & 1, wn = warp >> 1;

    const float* W = Wt + (size_t)w * DD * DD;
    const float* bias = (w == 0 ? b0 : w == 1 ? b1 : w == 2 ? b2 : b3);
    float* out = (w == 0 ? o0 : w == 1 ? o1 : w == 2 ? o2 : o3);

    uint32_t smb = (uint32_t)__cvta_generic_to_shared(sm);

    float c[4][4][4];
#pragma unroll
    for (int mi = 0; mi < 4; mi++)
#pragma unroll
        for (int ni = 0; ni < 4; ni++)
#pragma unroll
            for (int r = 0; r < 4; r++) c[mi][ni][r] = 0.f;

    auto load_stage = [&](int slot, int kt) {
        int k0 = kt * BK;
        uint32_t AsB = smb + (uint32_t)(slot * STAGE_FLOATS) * 4u;
        uint32_t BsB = AsB + AS_FLOATS * 4u;
#pragma unroll
        for (int s = 0; s < 4; s++) {
            int i = t + s * 256;
            int row = i >> 3, c4 = (i & 7) * 4;
            int grow = m0 + row;
            const float* src = A + (size_t)(grow < NN ? grow : 0) * DD + k0 + c4;
            cp16(AsB + (uint32_t)(row * SA + c4) * 4u, src);
        }
#pragma unroll
        for (int s = 0; s < 4; s++) {
            int i = t + s * 256;
            int row = i >> 5, c4 = (i & 31) * 4;
            const float* src = W + (size_t)(k0 + row) * DD + n0 + c4;
            cp16(BsB + (uint32_t)(row * SB + c4) * 4u, src);
        }
    };

    // prologue: 2 stages in flight
    load_stage(0, 0);
    cp_commit();
    load_stage(1, 1);
    cp_commit();

    for (int kt = 0; kt < NKT; kt++) {
        cp_wait1();          // stage kt landed
        __syncthreads();     // (also proves all warps finished reading slot (kt+2)%3 in iter kt-1)
        int cn = kt + 2;
        if (cn < NKT) load_stage(cn % GSTAGES, cn);
        cp_commit();         // one commit per iter keeps wait_group accounting constant
        const uint32_t* As = (const uint32_t*)(sm + (kt % GSTAGES) * STAGE_FLOATS);
        const uint32_t* Bs = As + AS_FLOATS;
#pragma unroll
        for (int ks = 0; ks < 4; ks++) {
            int k0s = ks * 8;
            uint32_t a[4][4], b[4][2];
#pragma unroll
            for (int mi = 0; mi < 4; mi++) {
                int mrow = wm * 64 + mi * 16 + g;
                const uint32_t* p = As + mrow * SA + k0s + qd;
                a[mi][0] = p[0];
                a[mi][1] = p[8 * SA];
                a[mi][2] = p[4];
                a[mi][3] = p[8 * SA + 4];
            }
#pragma unroll
            for (int ni = 0; ni < 4; ni++) {
                int ncol = wn * 32 + ni * 8 + g;
                const uint32_t* p = Bs + (k0s + qd) * SB + ncol;
                b[ni][0] = p[0];
                b[ni][1] = p[4 * SB];
            }
#pragma unroll
            for (int mi = 0; mi < 4; mi++)
#pragma unroll
                for (int ni = 0; ni < 4; ni++) mma_tf32(c[mi][ni], a[mi], b[ni]);
        }
    }

#pragma unroll
    for (int mi = 0; mi < 4; mi++) {
#pragma unroll
        for (int rh = 0; rh < 2; rh++) {
            int grow = m0 + wm * 64 + mi * 16 + rh * 8 + g;
            if (grow >= NN) continue;
            float* orow = out + (size_t)grow * DD + n0;
#pragma unroll
            for (int ni = 0; ni < 4; ni++) {
                int col = wn * 32 + ni * 8 + 2 * qd;
                float2 val;
                val.x = c[mi][ni][rh * 2 + 0] + bias[n0 + col];
                val.y = c[mi][ni][rh * 2 + 1] + bias[n0 + col + 1];
                *(float2*)(orow + col) = val;
            }
        }
    }
}

// ================= P[n, h*16+i] = sum_c q[n, h*C+c] * WeT[(h*C+c)*16 + i] =================
// 8 nodes/block, 512 threads; WeT staged in smem with per-head pad (conflict-free).
__global__ void __launch_bounds__(512) p_kernel(const float* __restrict__ q,
                                                const float* __restrict__ WeT,
                                                float* __restrict__ P) {
    __shared__ float qs[8][DD];          // 24 KB
    __shared__ float sW[HH * HPAD];      // 4*3088 floats = 49.4 KB
    int t = threadIdx.x;
    int nb = blockIdx.x * 8;
    for (int idx = t; idx < 8 * DD; idx += 512) {
        int nn = nb + (idx / DD);
        qs[idx / DD][idx % DD] = (nn < NN) ? q[(size_t)nn * DD + (idx % DD)] : 0.f;
    }
    for (int idx = t; idx < HH * CC * EDIMF; idx += 512) {
        int h = idx / (CC * EDIMF);
        int rem = idx - h * (CC * EDIMF);
        sW[h * HPAD + rem] = WeT[idx];
    }
    __syncthreads();
    int local = t >> 6;
    int t64 = t & 63;
    int n = nb + local;
    if (n >= NN) return;
    int h = t64 >> 4, i = t64 & 15;
    const float* qq = qs[local] + h * CC;
    const float* wt = sW + h * HPAD + i;
    float s0 = 0.f, s1 = 0.f, s2 = 0.f, s3 = 0.f;
#pragma unroll 4
    for (int c = 0; c < CC; c += 4) {
        s0 = fmaf(qq[c + 0], wt[(c + 0) * 16], s0);
        s1 = fmaf(qq[c + 1], wt[(c + 1) * 16], s1);
        s2 = fmaf(qq[c + 2], wt[(c + 2) * 16], s2);
        s3 = fmaf(qq[c + 3], wt[(c + 3) * 16], s3);
    }
    P[(size_t)n * (HH * EDIMF) + t64] = (s0 + s1) + (s2 + s3);
}

// ================= fused attention: warp per node =================
__global__ void __launch_bounds__(256) node_fused_kernel(
    const float* __restrict__ q, const float* __restrict__ kk, const float* __restrict__ v,
    const float* __restrict__ skip, const float* __restrict__ efc, const float* __restrict__ P,
    const int* __restrict__ rowptr, const int* __restrict__ srcs,
    const float* __restrict__ We, float* __restrict__ galpha,
    float* __restrict__ out, int gelu) {
    __shared__ float abuf[8][WDEG * HH];
    __shared__ float Ssm[8][2 * 32];
    const int wid = threadIdx.x >> 5, lane = threadIdx.x & 31;
    const int n = blockIdx.x * 8 + wid;
    if (n >= NN) return;
    const int start = rowptr[n], end = rowptr[n + 1];
    const int deg = end - start;
    const unsigned FULL = 0xffffffffu;
    const int h = lane >> 3, lg = lane & 7;

    float* wp = (deg <= WDEG) ? abuf[wid] : (galpha + (size_t)start * HH);

    const float2* qr = (const float2*)(q + (size_t)n * DD + h * CC);
    float2 qv[12];
#pragma unroll
    for (int j = 0; j < 12; j++) qv[j] = qr[lg + 8 * j];
    const float p0 = P[(size_t)n * (HH * EDIMF) + h * EDIMF + lg];
    const float p1 = P[(size_t)n * (HH * EDIMF) + h * EDIMF + lg + 8];

    for (int base = 0; base < deg; base += 32) {
        int cnt = min(32, deg - base);
        int srcReg = (base + lane < deg) ? srcs[start + base + lane] : 0;
        for (int i = 0; i < cnt; i++) {
            int src = __shfl_sync(FULL, srcReg, i);
            int e = start + base + i;
            const float2* kr = (const float2*)(kk + (size_t)src * DD + h * CC);
            float s = 0.f;
#pragma unroll
            for (int j = 0; j < 12; j++) {
                float2 kv = kr[lg + 8 * j];
                s = fmaf(qv[j].x, kv.x, s);
                s = fmaf(qv[j].y, kv.y, s);
            }
            s = fmaf(efc[(size_t)e * EDIMF + lg], p0, s);
            s = fmaf(efc[(size_t)e * EDIMF + lg + 8], p1, s);
            s += __shfl_xor_sync(FULL, s, 1);
            s += __shfl_xor_sync(FULL, s, 2);
            s += __shfl_xor_sync(FULL, s, 4);
            if (lg == 0) wp[(base + i) * HH + h] = s * 0.07216878364870322f;
        }
    }
    __syncwarp();

    if (lane < HH) {
        float m = -1e30f;
        for (int i = 0; i < deg; i++) m = fmaxf(m, wp[i * HH + lane]);
        float ssum = 0.f;
        for (int i = 0; i < deg; i++) {
            float wv = expf(wp[i * HH + lane] - m);
            wp[i * HH + lane] = wv;
            ssum += wv;
        }
        float inv = 1.f / (ssum + 1e-16f);
        for (int i = 0; i < deg; i++) wp[i * HH + lane] *= inv;
    }
    __syncwarp();

    float acc[24];
#pragma unroll
    for (int j = 0; j < 24; j++) acc[j] = 0.f;
    float sa = 0.f, sb = 0.f;
    const int iA = lane & 15;
    const int hA = lane >> 4, hB = 2 + (lane >> 4);
    for (int base = 0; base < deg; base += 32) {
        int cnt = min(32, deg - base);
        int srcReg = (base + lane < deg) ? srcs[start + base + lane] : 0;
        for (int i = 0; i < cnt; i++) {
            int src = __shfl_sync(FULL, srcReg, i);
            int idx = base + i;
            const float* vr = v + (size_t)src * DD;
            float w0 = wp[idx * HH + 0];
            float w1 = wp[idx * HH + 1];
            float w2 = wp[idx * HH + 2];
            float w3 = wp[idx * HH + 3];
#pragma unroll
            for (int j = 0; j < 24; j++) {
                float wj = (j < 6) ? w0 : (j < 12) ? w1 : (j < 18) ? w2 : w3;
                acc[j] = fmaf(wj, vr[lane + 32 * j], acc[j]);
            }
            float efA = efc[(size_t)(start + idx) * EDIMF + iA];
            sa = fmaf(wp[idx * HH + hA], efA, sa);
            sb = fmaf(wp[idx * HH + hB], efA, sb);
        }
    }
    Ssm[wid][lane] = sa;
    Ssm[wid][lane + 32] = sb;
    __syncwarp();

    const float* sk = skip + (size_t)n * DD;
    float* orow = out + (size_t)n * DD;
#pragma unroll
    for (int j = 0; j < 24; j++) {
        int c = lane + 32 * j;
        int hh = j / 6;
        float val = acc[j];
#pragma unroll
        for (int i = 0; i < 16; i++)
            val = fmaf(Ssm[wid][hh * 16 + i], We[(size_t)i * DD + c], val);
        val += sk[c];
        if (gelu) {
            val = 0.5f * val * (1.f + erff(val * 0.7071067811865475f));
            val = round_tf32(val);
        }
        orow[c] = val;
    }
}

// ================= layernorm + global mean pool =================
__global__ void ln_pool_kernel(const float* __restrict__ h, float* __restrict__ out) {
    __shared__ float red[256];
    int t = threadIdx.x;
    float acc0 = 0.f, acc1 = 0.f, acc2 = 0.f;
    for (int n = blockIdx.x; n < NN; n += gridDim.x) {
        const float* row = h + (size_t)n * DD;
        float v0 = row[t], v1 = row[t + 256], v2 = row[t + 512];
        red[t] = v0 + v1 + v2;
        __syncthreads();
        for (int off = 128; off > 0; off >>= 1) {
            if (t < off) red[t] += red[t + off];
            __syncthreads();
        }
        float mu = red[0] * (1.f / DD);
        __syncthreads();
        float d0 = v0 - mu, d1 = v1 - mu, d2 = v2 - mu;
        red[t] = d0 * d0 + d1 * d1 + d2 * d2;
        __syncthreads();
        for (int off = 128; off > 0; off >>= 1) {
            if (t < off) red[t] += red[t + off];
            __syncthreads();
        }
        float rstd = rsqrtf(red[0] * (1.f / DD) + 1e-5f);
        __syncthreads();
        acc0 += d0 * rstd;
        acc1 += d1 * rstd;
        acc2 += d2 * rstd;
    }
    atomicAdd(&out[t], acc0);
    atomicAdd(&out[t + 256], acc1);
    atomicAdd(&out[t + 512], acc2);
}

__global__ void ln_final_kernel(float* __restrict__ out, const float* __restrict__ g,
                                const float* __restrict__ b) {
    int c = threadIdx.x + blockIdx.x * blockDim.x;
    if (c < DD) out[c] = out[c] * g[c] * (1.f / NN) + b[c];
}

// ================= launch =================
extern "C" void kernel_launch(void* const* d_in, const int* in_sizes, int n_in,
                              void* d_out, int out_size) {
    const float* x          = (const float*)d_in[0];
    const float* edge_attr  = (const float*)d_in[1];
    const int*   edge_index = (const int*)d_in[2];
    const float* rel_emb    = (const float*)d_in[3];
    const float* W_edge     = (const float*)d_in[4];
    const float* b_edge     = (const float*)d_in[5];
    const float* Wk         = (const float*)d_in[6];
    const float* bk         = (const float*)d_in[7];
    const float* Wq         = (const float*)d_in[8];
    const float* bq         = (const float*)d_in[9];
    const float* Wv         = (const float*)d_in[10];
    const float* bv         = (const float*)d_in[11];
    const float* We         = (const float*)d_in[12];
    const float* Wskip      = (const float*)d_in[13];
    const float* bskip      = (const float*)d_in[14];
    const float* ln_g       = (const float*)d_in[15];
    const float* ln_b       = (const float*)d_in[16];
    float* out = (float*)d_out;

    float *bufA, *bufB, *q, *k, *v, *skip, *ef, *efc, *alpha, *P, *WeT, *Wt;
    int *rowptr, *cnt, *cur, *srcidx;
    cudaGetSymbolAddress((void**)&bufA, g_bufA);
    cudaGetSymbolAddress((void**)&bufB, g_bufB);
    cudaGetSymbolAddress((void**)&q, g_q);
    cudaGetSymbolAddress((void**)&k, g_k);
    cudaGetSymbolAddress((void**)&v, g_v);
    cudaGetSymbolAddress((void**)&skip, g_skip);
    cudaGetSymbolAddress((void**)&ef, g_ef);
    cudaGetSymbolAddress((void**)&efc, g_efcsr);
    cudaGetSymbolAddress((void**)&alpha, g_alpha);
    cudaGetSymbolAddress((void**)&P, g_P);
    cudaGetSymbolAddress((void**)&WeT, g_WeT);
    cudaGetSymbolAddress((void**)&Wt, g_Wt);
    cudaGetSymbolAddress((void**)&rowptr, g_rowptr);
    cudaGetSymbolAddress((void**)&cnt, g_cnt);
    cudaGetSymbolAddress((void**)&cur, g_cur);
    cudaGetSymbolAddress((void**)&srcidx, g_srcidx);

    cudaFuncSetAttribute(gemm4_kernel, cudaFuncAttributeMaxDynamicSharedMemorySize, GEMM_SMEM);

    cudaMemsetAsync(cnt, 0, NN * sizeof(int));
    cudaMemsetAsync(cur, 0, NN * sizeof(int));
    // #1..#3 prep; gemm4(L0) = kernel #4 = ncu capture slot
    round_kernel<<<(WELEMS + XELEMS + 255) / 256, 256>>>(Wq, Wk, Wv, Wskip, x, Wt, bufB);  // #1
    prep1_kernel<<<(EE + 255) / 256, 256>>>(edge_index, cnt, We, WeT);                     // #2
    scan_kernel<<<1, 1024>>>(cnt, rowptr);                                                 // #3

    const float* hin = bufB;   // tf32-rounded x
    for (int l = 0; l < LL; l++) {
        const float* We_l = We + (size_t)l * EDIMF * DD;
        gemm4_kernel<<<dim3(24, (NN + BM - 1) / BM), 256, GEMM_SMEM>>>(                    // #4 (l=0)
            hin, Wt + (size_t)l * 4 * DD * DD,
            bq + (size_t)l * DD, bk + (size_t)l * DD, bv + (size_t)l * DD, bskip + (size_t)l * DD,
            q, k, v, skip);
        p_kernel<<<(NN + 7) / 8, 512>>>(q, WeT + (size_t)l * DD * EDIMF, P);
        if (l == 0) {
            ef_kernel<<<(EE + 255) / 256, 256>>>(edge_attr, rel_emb, W_edge, b_edge, ef);
            scatter_kernel<<<(EE + 255) / 256, 256>>>(edge_index, rowptr, cur, srcidx, ef, efc);
        }
        float* hout = (l & 1) ? bufB : bufA;
        node_fused_kernel<<<(NN + 7) / 8, 256>>>(q, k, v, skip, efc, P, rowptr, srcidx, We_l,
                                                 alpha, hout, (l < LL - 1) ? 1 : 0);
        hin = hout;
    }

    cudaMemsetAsync(out, 0, DD * sizeof(float));
    ln_pool_kernel<<<1024, 256>>>(hin, out);
    ln_final_kernel<<<3, 256>>>(out, ln_g, ln_b);
}

// round 11
// speedup vs baseline: 2.4808x; 1.0109x over previous
#include <cuda_runtime.h>
#include <cstdint>

#define NN 10000
#define EE 100000
#define DD 768
#define HH 4
#define CC 192
#define LL 3
#define EDIMF 16
#define NRELC 10

// GEMM tiling: block 128x128, 8 warps as 2(m) x 4(n), warp tile 64x32
#define BM 128
#define BN 128
#define BK 32
#define NKT (DD / BK)
#define GSTAGES 3
#define SA 36
#define SB 136
#define AS_FLOATS (BM * SA)
#define BS_FLOATS (BK * SB)
#define STAGE_FLOATS (AS_FLOATS + BS_FLOATS)
#define GEMM_SMEM (GSTAGES * STAGE_FLOATS * 4)   // ~105 KB -> 2 CTA/SM

#define WDEG 64

// ---------------- scratch (static device globals; no allocation) ----------------
__device__ float g_bufA[NN * DD];
__device__ float g_bufB[NN * DD];     // tf32-rounded x for layer 0, then hout(1)
__device__ float g_q[NN * DD];
__device__ float g_k[NN * DD];
__device__ float g_v[NN * DD];
__device__ float g_skip[NN * DD];
__device__ float g_Wt[LL * 4 * DD * DD];   // tf32-rounded weights [l][w][k][n]
__device__ float g_W5[LL * DD * 128];      // composed P-weight (cols 64..127 zero)
__device__ float g_b5[LL * 128];           // composed P-bias
__device__ float g_ef[EE * EDIMF];
__device__ float g_efcsr[EE * EDIMF];
__device__ float g_alpha[EE * HH];
__device__ float g_P[NN * HH * EDIMF];
__device__ int   g_rowptr[NN + 1];
__device__ int   g_cnt[NN];
__device__ int   g_cur[NN];
__device__ int   g_srcidx[EE];

// ---------------- helpers ----------------
__device__ __forceinline__ void cp16(uint32_t dst, const float* src) {
    asm volatile("cp.async.cg.shared.global [%0], [%1], 16;" ::"r"(dst),
                 "l"(__cvta_generic_to_global(src)));
}
__device__ __forceinline__ void cp_commit() { asm volatile("cp.async.commit_group;"); }
__device__ __forceinline__ void cp_wait1() { asm volatile("cp.async.wait_group 1;"); }

__device__ __forceinline__ uint32_t f2tf32(float f) {
    uint32_t u;
    asm("cvt.rna.tf32.f32 %0, %1;" : "=r"(u) : "f"(f));
    return u;
}
__device__ __forceinline__ float round_tf32(float f) { return __uint_as_float(f2tf32(f)); }

__device__ __forceinline__ void mma_tf32(float* c, const uint32_t* a, const uint32_t* b) {
    asm volatile(
        "mma.sync.aligned.m16n8k8.row.col.f32.tf32.tf32.f32 "
        "{%0,%1,%2,%3}, {%4,%5,%6,%7}, {%8,%9}, {%0,%1,%2,%3};"
        : "+f"(c[0]), "+f"(c[1]), "+f"(c[2]), "+f"(c[3])
        : "r"(a[0]), "r"(a[1]), "r"(a[2]), "r"(a[3]), "r"(b[0]), "r"(b[1]));
}

// ================= prep0: tf32-round all GEMM weights + x =================
#define WELEMS (LL * 4 * DD * DD / 4)
#define XELEMS (NN * DD / 4)
__global__ void round_kernel(const float* __restrict__ Wq, const float* __restrict__ Wk,
                             const float* __restrict__ Wv, const float* __restrict__ Ws,
                             const float* __restrict__ x,
                             float* __restrict__ Wt, float* __restrict__ xr) {
    int idx = blockIdx.x * blockDim.x + threadIdx.x;
    if (idx < WELEMS) {
        int z = idx / (DD * DD / 4);
        int rem = idx % (DD * DD / 4);
        int l = z >> 2, w = z & 3;
        const float* W = (w == 0 ? Wq : w == 1 ? Wk : w == 2 ? Wv : Ws) + (size_t)l * DD * DD;
        float4 val = ((const float4*)W)[rem];
        val.x = round_tf32(val.x); val.y = round_tf32(val.y);
        val.z = round_tf32(val.z); val.w = round_tf32(val.w);
        ((float4*)Wt)[idx] = val;
    } else if (idx < WELEMS + XELEMS) {
        int i = idx - WELEMS;
        float4 val = ((const float4*)x)[i];
        val.x = round_tf32(val.x); val.y = round_tf32(val.y);
        val.z = round_tf32(val.z); val.w = round_tf32(val.w);
        ((float4*)xr)[i] = val;
    }
}

// ================= prep1: edge count for CSR =================
__global__ void count_kernel(const int* __restrict__ edge_index, int* __restrict__ cnt) {
    int e = blockIdx.x * blockDim.x + threadIdx.x;
    if (e < EE) atomicAdd(&cnt[edge_index[EE + e]], 1);
}

// ================= prep2: compose W5 = Wq@Wp (block-diag We), b5 = bq@Wp =================
// P[n,j] (j = h*16+i, h=j>>4) = sum_{c in head h} q[n, h*C+c] * We[i, h*C+c]
//                             = hin @ W5 + b5   with q = hin@Wq + bq  (exact algebra)
__global__ void compose_kernel(const float* __restrict__ Wq, const float* __restrict__ bq,
                               const float* __restrict__ We,
                               float* __restrict__ W5, float* __restrict__ b5) {
    int idx = blockIdx.x * blockDim.x + threadIdx.x;
    const int total = LL * DD * 128;
    if (idx < total) {
        int l = idx / (DD * 128);
        int rem = idx % (DD * 128);
        int k = rem >> 7, j = rem & 127;
        float s = 0.f;
        if (j < 64) {
            int h = j >> 4, i = j & 15;
            const float* wq = Wq + (size_t)l * DD * DD + (size_t)k * DD + h * CC;
            const float* we = We + (size_t)l * EDIMF * DD + (size_t)i * DD + h * CC;
#pragma unroll 4
            for (int c = 0; c < CC; c++) s = fmaf(wq[c], we[c], s);
            s = round_tf32(s);
        }
        W5[idx] = s;
    } else if (idx < total + LL * 128) {
        int r = idx - total;
        int l = r >> 7, j = r & 127;
        float s = 0.f;
        if (j < 64) {
            int h = j >> 4, i = j & 15;
            const float* bb = bq + (size_t)l * DD + h * CC;
            const float* we = We + (size_t)l * EDIMF * DD + (size_t)i * DD + h * CC;
#pragma unroll 4
            for (int c = 0; c < CC; c++) s = fmaf(bb[c], we[c], s);
        }
        b5[r] = s;
    }
}

// ================= edge feature projection =================
__global__ void ef_kernel(const float* __restrict__ edge_attr, const float* __restrict__ rel_emb,
                          const float* __restrict__ W_edge, const float* __restrict__ b_edge,
                          float* __restrict__ ef) {
    __shared__ float sW[EDIMF * EDIMF];
    __shared__ float sB[EDIMF];
    __shared__ float sR[NRELC * (EDIMF - 1)];
    int t = threadIdx.x;
    if (t < EDIMF * EDIMF) sW[t] = W_edge[t];
    if (t < EDIMF) sB[t] = b_edge[t];
    if (t < NRELC * (EDIMF - 1)) sR[t] = rel_emb[t];
    __syncthreads();
    int e = blockIdx.x * blockDim.x + t;
    if (e >= EE) return;
    int r = (int)edge_attr[2 * e];
    r = min(max(r, 0), NRELC - 1);
    float feat[EDIMF];
#pragma unroll
    for (int i = 0; i < EDIMF - 1; i++) feat[i] = sR[r * (EDIMF - 1) + i];
    feat[EDIMF - 1] = edge_attr[2 * e + 1];
#pragma unroll
    for (int j = 0; j < EDIMF; j++) {
        float s = sB[j];
#pragma unroll
        for (int i = 0; i < EDIMF; i++) s += feat[i] * sW[i * EDIMF + j];
        ef[(size_t)e * EDIMF + j] = s;
    }
}

// ================= CSR scan =================
__global__ void scan_kernel(const int* __restrict__ cnt, int* __restrict__ rowptr) {
    __shared__ int s[1024];
    int t = threadIdx.x;
    int carry = 0;
    if (t == 0) rowptr[0] = 0;
    for (int base = 0; base < NN; base += 1024) {
        int i = base + t;
        s[t] = (i < NN) ? cnt[i] : 0;
        __syncthreads();
        for (int off = 1; off < 1024; off <<= 1) {
            int add = (t >= off) ? s[t - off] : 0;
            __syncthreads();
            s[t] += add;
            __syncthreads();
        }
        if (i < NN) rowptr[i + 1] = carry + s[t];
        int tot = s[1023];
        __syncthreads();
        carry += tot;
    }
}

__global__ void scatter_kernel(const int* __restrict__ edge_index, const int* __restrict__ rowptr,
                               int* __restrict__ cur, int* __restrict__ srcs,
                               const float* __restrict__ ef, float* __restrict__ efc) {
    int e = blockIdx.x * blockDim.x + threadIdx.x;
    if (e >= EE) return;
    int dst = edge_index[EE + e];
    int pos = rowptr[dst] + atomicAdd(&cur[dst], 1);
    srcs[pos] = edge_index[e];
    const float4* s = (const float4*)(ef + (size_t)e * EDIMF);
    float4* d = (float4*)(efc + (size_t)pos * EDIMF);
    d[0] = s[0]; d[1] = s[1]; d[2] = s[2]; d[3] = s[3];
}

// ================= fused Q/K/V/Skip/P GEMM via mma.sync tf32 =================
// grid (25, 79): bx<24 -> weight bx/6, col tile bx%6; bx==24 -> P output (composed weight).
__global__ void __launch_bounds__(256, 2) gemm5_kernel(
    const float* __restrict__ A, const float* __restrict__ Wt,
    const float* __restrict__ W5, const float* __restrict__ b5,
    const float* __restrict__ b0, const float* __restrict__ b1,
    const float* __restrict__ b2, const float* __restrict__ b3,
    float* __restrict__ o0, float* __restrict__ o1,
    float* __restrict__ o2, float* __restrict__ o3,
    float* __restrict__ oP) {
    extern __shared__ float sm[];
    const int t = threadIdx.x;
    const int warp = t >> 5, lane = t & 31;
    const int g = lane >> 2, qd = lane & 3;
    const int w = blockIdx.x / 6;           // 0..4
    const int n0 = (w < 4) ? (blockIdx.x % 6) * BN : 0;
    const int m0 = blockIdx.y * BM;
    const int wm = warp & 1, wn = warp >> 1;

    const float* W;
    const float* bias;
    float* out;
    int ldw, ostride;
    if (w < 4) {
        W = Wt + (size_t)w * DD * DD;
        bias = (w == 0 ? b0 : w == 1 ? b1 : w == 2 ? b2 : b3);
        out = (w == 0 ? o0 : w == 1 ? o1 : w == 2 ? o2 : o3);
        ldw = DD; ostride = DD;
    } else {
        W = W5; bias = b5; out = oP;
        ldw = 128; ostride = 64;
    }

    uint32_t smb = (uint32_t)__cvta_generic_to_shared(sm);

    float c[4][4][4];
#pragma unroll
    for (int mi = 0; mi < 4; mi++)
#pragma unroll
        for (int ni = 0; ni < 4; ni++)
#pragma unroll
            for (int r = 0; r < 4; r++) c[mi][ni][r] = 0.f;

    auto load_stage = [&](int slot, int kt) {
        int k0 = kt * BK;
        uint32_t AsB = smb + (uint32_t)(slot * STAGE_FLOATS) * 4u;
        uint32_t BsB = AsB + AS_FLOATS * 4u;
#pragma unroll
        for (int s = 0; s < 4; s++) {
            int i = t + s * 256;
            int row = i >> 3, c4 = (i & 7) * 4;
            int grow = m0 + row;
            const float* src = A + (size_t)(grow < NN ? grow : 0) * DD + k0 + c4;
            cp16(AsB + (uint32_t)(row * SA + c4) * 4u, src);
        }
#pragma unroll
        for (int s = 0; s < 4; s++) {
            int i = t + s * 256;
            int row = i >> 5, c4 = (i & 31) * 4;
            const float* src = W + (size_t)(k0 + row) * ldw + n0 + c4;
            cp16(BsB + (uint32_t)(row * SB + c4) * 4u, src);
        }
    };

    load_stage(0, 0);
    cp_commit();
    load_stage(1, 1);
    cp_commit();

    for (int kt = 0; kt < NKT; kt++) {
        cp_wait1();
        __syncthreads();
        int cn = kt + 2;
        if (cn < NKT) load_stage(cn % GSTAGES, cn);
        cp_commit();
        const uint32_t* As = (const uint32_t*)(sm + (kt % GSTAGES) * STAGE_FLOATS);
        const uint32_t* Bs = As + AS_FLOATS;
#pragma unroll
        for (int ks = 0; ks < 4; ks++) {
            int k0s = ks * 8;
            uint32_t a[4][4], b[4][2];
#pragma unroll
            for (int mi = 0; mi < 4; mi++) {
                int mrow = wm * 64 + mi * 16 + g;
                const uint32_t* p = As + mrow * SA + k0s + qd;
                a[mi][0] = p[0];
                a[mi][1] = p[8 * SA];
                a[mi][2] = p[4];
                a[mi][3] = p[8 * SA + 4];
            }
#pragma unroll
            for (int ni = 0; ni < 4; ni++) {
                int ncol = wn * 32 + ni * 8 + g;
                const uint32_t* p = Bs + (k0s + qd) * SB + ncol;
                b[ni][0] = p[0];
                b[ni][1] = p[4 * SB];
            }
#pragma unroll
            for (int mi = 0; mi < 4; mi++)
#pragma unroll
                for (int ni = 0; ni < 4; ni++) mma_tf32(c[mi][ni], a[mi], b[ni]);
        }
    }

#pragma unroll
    for (int mi = 0; mi < 4; mi++) {
#pragma unroll
        for (int rh = 0; rh < 2; rh++) {
            int grow = m0 + wm * 64 + mi * 16 + rh * 8 + g;
            if (grow >= NN) continue;
            float* orow = out + (size_t)grow * ostride + n0;
#pragma unroll
            for (int ni = 0; ni < 4; ni++) {
                int col = wn * 32 + ni * 8 + 2 * qd;
                if (w == 4 && col >= 64) continue;   // P has 64 real cols
                float2 val;
                val.x = c[mi][ni][rh * 2 + 0] + bias[n0 + col];
                val.y = c[mi][ni][rh * 2 + 1] + bias[n0 + col + 1];
                *(float2*)(orow + col) = val;
            }
        }
    }
}

// ================= fused attention: warp per node =================
__global__ void __launch_bounds__(256) node_fused_kernel(
    const float* __restrict__ q, const float* __restrict__ kk, const float* __restrict__ v,
    const float* __restrict__ skip, const float* __restrict__ efc, const float* __restrict__ P,
    const int* __restrict__ rowptr, const int* __restrict__ srcs,
    const float* __restrict__ We, float* __restrict__ galpha,
    float* __restrict__ out, int gelu) {
    __shared__ float abuf[8][WDEG * HH];
    __shared__ float Ssm[8][2 * 32];
    const int wid = threadIdx.x >> 5, lane = threadIdx.x & 31;
    const int n = blockIdx.x * 8 + wid;
    if (n >= NN) return;
    const int start = rowptr[n], end = rowptr[n + 1];
    const int deg = end - start;
    const unsigned FULL = 0xffffffffu;
    const int h = lane >> 3, lg = lane & 7;

    float* wp = (deg <= WDEG) ? abuf[wid] : (galpha + (size_t)start * HH);

    const float2* qr = (const float2*)(q + (size_t)n * DD + h * CC);
    float2 qv[12];
#pragma unroll
    for (int j = 0; j < 12; j++) qv[j] = qr[lg + 8 * j];
    const float p0 = P[(size_t)n * (HH * EDIMF) + h * EDIMF + lg];
    const float p1 = P[(size_t)n * (HH * EDIMF) + h * EDIMF + lg + 8];

    for (int base = 0; base < deg; base += 32) {
        int cnt = min(32, deg - base);
        int srcReg = (base + lane < deg) ? srcs[start + base + lane] : 0;
        for (int i = 0; i < cnt; i++) {
            int src = __shfl_sync(FULL, srcReg, i);
            int e = start + base + i;
            const float2* kr = (const float2*)(kk + (size_t)src * DD + h * CC);
            float s = 0.f;
#pragma unroll
            for (int j = 0; j < 12; j++) {
                float2 kv = kr[lg + 8 * j];
                s = fmaf(qv[j].x, kv.x, s);
                s = fmaf(qv[j].y, kv.y, s);
            }
            s = fmaf(efc[(size_t)e * EDIMF + lg], p0, s);
            s = fmaf(efc[(size_t)e * EDIMF + lg + 8], p1, s);
            s += __shfl_xor_sync(FULL, s, 1);
            s += __shfl_xor_sync(FULL, s, 2);
            s += __shfl_xor_sync(FULL, s, 4);
            if (lg == 0) wp[(base + i) * HH + h] = s * 0.07216878364870322f;
        }
    }
    __syncwarp();

    if (lane < HH) {
        float m = -1e30f;
        for (int i = 0; i < deg; i++) m = fmaxf(m, wp[i * HH + lane]);
        float ssum = 0.f;
        for (int i = 0; i < deg; i++) {
            float wv = expf(wp[i * HH + lane] - m);
            wp[i * HH + lane] = wv;
            ssum += wv;
        }
        float inv = 1.f / (ssum + 1e-16f);
        for (int i = 0; i < deg; i++) wp[i * HH + lane] *= inv;
    }
    __syncwarp();

    float acc[24];
#pragma unroll
    for (int j = 0; j < 24; j++) acc[j] = 0.f;
    float sa = 0.f, sb = 0.f;
    const int iA = lane & 15;
    const int hA = lane >> 4, hB = 2 + (lane >> 4);
    for (int base = 0; base < deg; base += 32) {
        int cnt = min(32, deg - base);
        int srcReg = (base + lane < deg) ? srcs[start + base + lane] : 0;
        for (int i = 0; i < cnt; i++) {
            int src = __shfl_sync(FULL, srcReg, i);
            int idx = base + i;
            const float* vr = v + (size_t)src * DD;
            float w0 = wp[idx * HH + 0];
            float w1 = wp[idx * HH + 1];
            float w2 = wp[idx * HH + 2];
            float w3 = wp[idx * HH + 3];
#pragma unroll
            for (int j = 0; j < 24; j++) {
                float wj = (j < 6) ? w0 : (j < 12) ? w1 : (j < 18) ? w2 : w3;
                acc[j] = fmaf(wj, vr[lane + 32 * j], acc[j]);
            }
            float efA = efc[(size_t)(start + idx) * EDIMF + iA];
            sa = fmaf(wp[idx * HH + hA], efA, sa);
            sb = fmaf(wp[idx * HH + hB], efA, sb);
        }
    }
    Ssm[wid][lane] = sa;
    Ssm[wid][lane + 32] = sb;
    __syncwarp();

    const float* sk = skip + (size_t)n * DD;
    float* orow = out + (size_t)n * DD;
#pragma unroll
    for (int j = 0; j < 24; j++) {
        int c = lane + 32 * j;
        int hh = j / 6;
        float val = acc[j];
#pragma unroll
        for (int i = 0; i < 16; i++)
            val = fmaf(Ssm[wid][hh * 16 + i], We[(size_t)i * DD + c], val);
        val += sk[c];
        if (gelu) {
            val = 0.5f * val * (1.f + erff(val * 0.7071067811865475f));
            val = round_tf32(val);
        }
        orow[c] = val;
    }
}

// ================= layernorm + global mean pool =================
__global__ void ln_pool_kernel(const float* __restrict__ h, float* __restrict__ out) {
    __shared__ float red[256];
    int t = threadIdx.x;
    float acc0 = 0.f, acc1 = 0.f, acc2 = 0.f;
    for (int n = blockIdx.x; n < NN; n += gridDim.x) {
        const float* row = h + (size_t)n * DD;
        float v0 = row[t], v1 = row[t + 256], v2 = row[t + 512];
        red[t] = v0 + v1 + v2;
        __syncthreads();
        for (int off = 128; off > 0; off >>= 1) {
            if (t < off) red[t] += red[t + off];
            __syncthreads();
        }
        float mu = red[0] * (1.f / DD);
        __syncthreads();
        float d0 = v0 - mu, d1 = v1 - mu, d2 = v2 - mu;
        red[t] = d0 * d0 + d1 * d1 + d2 * d2;
        __syncthreads();
        for (int off = 128; off > 0; off >>= 1) {
            if (t < off) red[t] += red[t + off];
            __syncthreads();
        }
        float rstd = rsqrtf(red[0] * (1.f / DD) + 1e-5f);
        __syncthreads();
        acc0 += d0 * rstd;
        acc1 += d1 * rstd;
        acc2 += d2 * rstd;
    }
    atomicAdd(&out[t], acc0);
    atomicAdd(&out[t + 256], acc1);
    atomicAdd(&out[t + 512], acc2);
}

__global__ void ln_final_kernel(float* __restrict__ out, const float* __restrict__ g,
                                const float* __restrict__ b) {
    int c = threadIdx.x + blockIdx.x * blockDim.x;
    if (c < DD) out[c] = out[c] * g[c] * (1.f / NN) + b[c];
}

// ================= launch =================
extern "C" void kernel_launch(void* const* d_in, const int* in_sizes, int n_in,
                              void* d_out, int out_size) {
    const float* x          = (const float*)d_in[0];
    const float* edge_attr  = (const float*)d_in[1];
    const int*   edge_index = (const int*)d_in[2];
    const float* rel_emb    = (const float*)d_in[3];
    const float* W_edge     = (const float*)d_in[4];
    const float* b_edge     = (const float*)d_in[5];
    const float* Wk         = (const float*)d_in[6];
    const float* bk         = (const float*)d_in[7];
    const float* Wq         = (const float*)d_in[8];
    const float* bq         = (const float*)d_in[9];
    const float* Wv         = (const float*)d_in[10];
    const float* bv         = (const float*)d_in[11];
    const float* We         = (const float*)d_in[12];
    const float* Wskip      = (const float*)d_in[13];
    const float* bskip      = (const float*)d_in[14];
    const float* ln_g       = (const float*)d_in[15];
    const float* ln_b       = (const float*)d_in[16];
    float* out = (float*)d_out;

    float *bufA, *bufB, *q, *k, *v, *skip, *ef, *efc, *alpha, *P, *Wt, *W5, *b5;
    int *rowptr, *cnt, *cur, *srcidx;
    cudaGetSymbolAddress((void**)&bufA, g_bufA);
    cudaGetSymbolAddress((void**)&bufB, g_bufB);
    cudaGetSymbolAddress((void**)&q, g_q);
    cudaGetSymbolAddress((void**)&k, g_k);
    cudaGetSymbolAddress((void**)&v, g_v);
    cudaGetSymbolAddress((void**)&skip, g_skip);
    cudaGetSymbolAddress((void**)&ef, g_ef);
    cudaGetSymbolAddress((void**)&efc, g_efcsr);
    cudaGetSymbolAddress((void**)&alpha, g_alpha);
    cudaGetSymbolAddress((void**)&P, g_P);
    cudaGetSymbolAddress((void**)&Wt, g_Wt);
    cudaGetSymbolAddress((void**)&W5, g_W5);
    cudaGetSymbolAddress((void**)&b5, g_b5);
    cudaGetSymbolAddress((void**)&rowptr, g_rowptr);
    cudaGetSymbolAddress((void**)&cnt, g_cnt);
    cudaGetSymbolAddress((void**)&cur, g_cur);
    cudaGetSymbolAddress((void**)&srcidx, g_srcidx);

    cudaFuncSetAttribute(gemm5_kernel, cudaFuncAttributeMaxDynamicSharedMemorySize, GEMM_SMEM);

    cudaMemsetAsync(cnt, 0, NN * sizeof(int));
    cudaMemsetAsync(cur, 0, NN * sizeof(int));
    // #1..#3 prep; gemm5(L0) = kernel #4 = ncu capture slot
    round_kernel<<<(WELEMS + XELEMS + 255) / 256, 256>>>(Wq, Wk, Wv, Wskip, x, Wt, bufB);    // #1
    count_kernel<<<(EE + 255) / 256, 256>>>(edge_index, cnt);                                 // #2
    compose_kernel<<<(LL * DD * 128 + LL * 128 + 255) / 256, 256>>>(Wq, bq, We, W5, b5);      // #3

    const float* hin = bufB;   // tf32-rounded x
    for (int l = 0; l < LL; l++) {
        const float* We_l = We + (size_t)l * EDIMF * DD;
        gemm5_kernel<<<dim3(25, (NN + BM - 1) / BM), 256, GEMM_SMEM>>>(                       // #4 (l=0)
            hin, Wt + (size_t)l * 4 * DD * DD,
            W5 + (size_t)l * DD * 128, b5 + (size_t)l * 128,
            bq + (size_t)l * DD, bk + (size_t)l * DD, bv + (size_t)l * DD, bskip + (size_t)l * DD,
            q, k, v, skip, P);
        if (l == 0) {
            scan_kernel<<<1, 1024>>>(cnt, rowptr);
            ef_kernel<<<(EE + 255) / 256, 256>>>(edge_attr, rel_emb, W_edge, b_edge, ef);
            scatter_kernel<<<(EE + 255) / 256, 256>>>(edge_index, rowptr, cur, srcidx, ef, efc);
        }
        float* hout = (l & 1) ? bufB : bufA;
        node_fused_kernel<<<(NN + 7) / 8, 256>>>(q, k, v, skip, efc, P, rowptr, srcidx, We_l,
                                                 alpha, hout, (l < LL - 1) ? 1 : 0);
        hin = hout;
    }

    cudaMemsetAsync(out, 0, DD * sizeof(float));
    ln_pool_kernel<<<1024, 256>>>(hin, out);
    ln_final_kernel<<<3, 256>>>(out, ln_g, ln_b);
}